// round 5
// baseline (speedup 1.0000x reference)
#include <cuda_runtime.h>
#include <math.h>
#include <stdint.h>

#define B_SZ 128
#define S_SZ 256
#define HID  256
#define MS   (B_SZ * S_SZ)   // 32768 rows
#define NBLK 128             // persistent LSTM grid (<=148 SMs -> all resident)

// ---------------- scratch (device globals; no allocation allowed) ----------------
__device__ float g_st1[MS * 256];
__device__ float g_st2[MS * 512];
__device__ float g_st3[MS * 1024];
__device__ float g_u  [MS * 1024];
__device__ float g_h  [2 * B_SZ * HID];
__device__ float g_c  [2 * B_SZ * HID];
__device__ unsigned g_cnt2[16];
__device__ unsigned g_gen2[16];

// ============================================================================
// fp32 SGEMM (used only for se1, K=67): BM=128,BN=128,BK=8, double-buffered.
// ============================================================================
template<bool RELU, bool ACC>
__global__ __launch_bounds__(256, 2)
void sgemm_kernel(const float* __restrict__ A, const float* __restrict__ Bm,
                  const float* __restrict__ bias, float* __restrict__ C,
                  int M, int N, int K)
{
    __shared__ float As[2][8][128];
    __shared__ float Bs[2][8][128];

    const int tid = threadIdx.x;
    const int tx  = tid & 15;
    const int ty  = tid >> 4;
    const int bm  = blockIdx.y * 128;
    const int bn  = blockIdx.x * 128;

    float acc[8][8] = {};

    const int a_base = tid * 4;
    const int am = a_base >> 3;
    const int ak = a_base & 7;
    const int bk = tid >> 5;
    const int bn4 = (tid & 31) * 4;

    float ra[4];
    float4 rb;

    auto ldreg = [&](int k0) {
        #pragma unroll
        for (int i = 0; i < 4; i++) {
            int gk = k0 + ak + i;
            ra[i] = (gk < K) ? A[(size_t)(bm + am) * K + gk] : 0.f;
        }
        if (k0 + bk < K) rb = *(const float4*)&Bm[(size_t)(k0 + bk) * N + bn + bn4];
        else             rb = make_float4(0.f, 0.f, 0.f, 0.f);
    };
    auto stsm = [&](int buf) {
        #pragma unroll
        for (int i = 0; i < 4; i++) As[buf][ak + i][am] = ra[i];
        *(float4*)&Bs[buf][bk][bn4] = rb;
    };

    ldreg(0);
    stsm(0);
    __syncthreads();

    const int nT = (K + 7) / 8;
    for (int t = 0; t < nT; t++) {
        const int buf = t & 1;
        if (t + 1 < nT) ldreg((t + 1) * 8);

        #pragma unroll
        for (int kk = 0; kk < 8; kk++) {
            float4 a0 = *(const float4*)&As[buf][kk][ty * 8];
            float4 a1 = *(const float4*)&As[buf][kk][ty * 8 + 4];
            float4 b0 = *(const float4*)&Bs[buf][kk][tx * 8];
            float4 b1 = *(const float4*)&Bs[buf][kk][tx * 8 + 4];
            float av[8] = {a0.x, a0.y, a0.z, a0.w, a1.x, a1.y, a1.z, a1.w};
            float bv[8] = {b0.x, b0.y, b0.z, b0.w, b1.x, b1.y, b1.z, b1.w};
            #pragma unroll
            for (int i = 0; i < 8; i++)
                #pragma unroll
                for (int j = 0; j < 8; j++)
                    acc[i][j] += av[i] * bv[j];
        }

        if (t + 1 < nT) {
            stsm(1 - buf);
            __syncthreads();
        }
    }

    #pragma unroll
    for (int i = 0; i < 8; i++) {
        const size_t row = (size_t)(bm + ty * 8 + i);
        #pragma unroll
        for (int j = 0; j < 8; j += 4) {
            const int col = bn + tx * 8 + j;
            float4 v = make_float4(acc[i][j], acc[i][j + 1], acc[i][j + 2], acc[i][j + 3]);
            if (bias) {
                v.x += bias[col];     v.y += bias[col + 1];
                v.z += bias[col + 2]; v.w += bias[col + 3];
            }
            if (ACC) {
                float4 o = *(const float4*)&C[row * N + col];
                v.x += o.x; v.y += o.y; v.z += o.z; v.w += o.w;
            }
            if (RELU) {
                v.x = fmaxf(v.x, 0.f); v.y = fmaxf(v.y, 0.f);
                v.z = fmaxf(v.z, 0.f); v.w = fmaxf(v.w, 0.f);
            }
            *(float4*)&C[row * N + col] = v;
        }
    }
}

// ============================================================================
// 3xTF32 tensor-core GEMM: C = act(A[M,K] @ B[K,N] + bias (+C))
// BM=128, BN=128, BK=16. 256 threads = 8 warps (2x4). Warp tile 64x32 via
// m16n8k8 mma.sync. Split a = hi + lo (tf32 each); D += aH*bH + aH*bL + aL*bH
// (residual ~2^-22 relative). Requires K%16==0, N%128==0, M%128==0.
// ============================================================================
#define TSTR 136                      // smem row stride (floats): conflict-free
#define TBUF 2176                     // 16*136 floats per matrix per buffer

__device__ __forceinline__ uint32_t f2tf32(float a) {
    uint32_t r; asm("cvt.rna.tf32.f32 %0, %1;" : "=r"(r) : "f"(a)); return r;
}

#define MMA_TF32(cc, aa, bb)                                                   \
    asm volatile("mma.sync.aligned.m16n8k8.row.col.f32.tf32.tf32.f32 "         \
        "{%0,%1,%2,%3}, {%4,%5,%6,%7}, {%8,%9}, {%0,%1,%2,%3};"                \
        : "+f"((cc)[0]), "+f"((cc)[1]), "+f"((cc)[2]), "+f"((cc)[3])           \
        : "r"((aa)[0]), "r"((aa)[1]), "r"((aa)[2]), "r"((aa)[3]),              \
          "r"((bb)[0]), "r"((bb)[1]))

template<bool RELU, bool ACC>
__global__ __launch_bounds__(256, 1)
void tf32_gemm(const float* __restrict__ A, const float* __restrict__ Bm,
               const float* __restrict__ bias, float* __restrict__ C,
               int M, int N, int K)
{
    extern __shared__ float smx[];
    // per buffer: [AH | AL | BH | BL], each TBUF floats, layout [k][m] / [k][n]
    const int tid  = threadIdx.x;
    const int lane = tid & 31;
    const int wid  = tid >> 5;
    const int wm   = wid >> 2;            // 0..1
    const int wn   = wid & 3;             // 0..3
    const int r    = lane >> 2;           // groupID 0..7
    const int cl4  = lane & 3;            // threadID_in_group 0..3
    const int bm   = blockIdx.y * 128;
    const int bn   = blockIdx.x * 128;
    const int m_base = wm * 64;
    const int n_base = wn * 32;

    const int la_m  = tid >> 1;           // A row 0..127
    const int la_k  = (tid & 1) * 8;      // A k-seg 0/8
    const int lb_k  = tid >> 4;           // B k row 0..15
    const int lb_n  = (tid & 15) * 8;     // B col seg

    float4 ra0, ra1, rb0, rb1;
    auto ldreg = [&](int k0) {
        const float* ap = A + (size_t)(bm + la_m) * K + k0 + la_k;
        ra0 = *(const float4*)ap;
        ra1 = *(const float4*)(ap + 4);
        const float* bp = Bm + (size_t)(k0 + lb_k) * N + bn + lb_n;
        rb0 = *(const float4*)bp;
        rb1 = *(const float4*)(bp + 4);
    };
    auto stsm = [&](int buf) {
        float* AH = smx + buf * 4 * TBUF;
        float* AL = AH + TBUF;
        float* BH = AL + TBUF;
        float* BL = BH + TBUF;
        float av[8] = {ra0.x, ra0.y, ra0.z, ra0.w, ra1.x, ra1.y, ra1.z, ra1.w};
        #pragma unroll
        for (int i = 0; i < 8; i++) {
            uint32_t h = f2tf32(av[i]);
            float lo   = av[i] - __uint_as_float(h);
            AH[(la_k + i) * TSTR + la_m] = __uint_as_float(h);
            AL[(la_k + i) * TSTR + la_m] = __uint_as_float(f2tf32(lo));
        }
        float bv[8] = {rb0.x, rb0.y, rb0.z, rb0.w, rb1.x, rb1.y, rb1.z, rb1.w};
        float4 h4, l4;
        float* hp = (float*)&h4; float* lp = (float*)&l4;
        #pragma unroll
        for (int i = 0; i < 4; i++) {
            uint32_t h = f2tf32(bv[i]);
            hp[i] = __uint_as_float(h);
            lp[i] = __uint_as_float(f2tf32(bv[i] - __uint_as_float(h)));
        }
        *(float4*)&BH[lb_k * TSTR + lb_n] = h4;
        *(float4*)&BL[lb_k * TSTR + lb_n] = l4;
        #pragma unroll
        for (int i = 0; i < 4; i++) {
            uint32_t h = f2tf32(bv[4 + i]);
            hp[i] = __uint_as_float(h);
            lp[i] = __uint_as_float(f2tf32(bv[4 + i] - __uint_as_float(h)));
        }
        *(float4*)&BH[lb_k * TSTR + lb_n + 4] = h4;
        *(float4*)&BL[lb_k * TSTR + lb_n + 4] = l4;
    };

    float cacc[4][4][4] = {};

    ldreg(0);
    stsm(0);
    __syncthreads();

    const int nT = K / 16;
    for (int t = 0; t < nT; t++) {
        const int buf = t & 1;
        if (t + 1 < nT) ldreg((t + 1) * 16);

        const uint32_t* AHu = (const uint32_t*)(smx + buf * 4 * TBUF);
        const uint32_t* ALu = AHu + TBUF;
        const uint32_t* BHu = ALu + TBUF;
        const uint32_t* BLu = BHu + TBUF;

        #pragma unroll
        for (int kk = 0; kk < 16; kk += 8) {
            const int base0 = (kk + cl4) * TSTR;
            const int base4 = (kk + cl4 + 4) * TSTR;
            uint32_t aH[4][4], aL[4][4], bH[4][2], bL[4][2];
            #pragma unroll
            for (int mt = 0; mt < 4; mt++) {
                const int rl = m_base + mt * 16 + r;
                aH[mt][0] = AHu[base0 + rl];     aH[mt][1] = AHu[base0 + rl + 8];
                aH[mt][2] = AHu[base4 + rl];     aH[mt][3] = AHu[base4 + rl + 8];
                aL[mt][0] = ALu[base0 + rl];     aL[mt][1] = ALu[base0 + rl + 8];
                aL[mt][2] = ALu[base4 + rl];     aL[mt][3] = ALu[base4 + rl + 8];
            }
            #pragma unroll
            for (int nt = 0; nt < 4; nt++) {
                const int cc = n_base + nt * 8 + r;
                bH[nt][0] = BHu[base0 + cc];     bH[nt][1] = BHu[base4 + cc];
                bL[nt][0] = BLu[base0 + cc];     bL[nt][1] = BLu[base4 + cc];
            }
            #pragma unroll
            for (int mt = 0; mt < 4; mt++)
                #pragma unroll
                for (int nt = 0; nt < 4; nt++) {
                    MMA_TF32(cacc[mt][nt], aH[mt], bH[nt]);
                    MMA_TF32(cacc[mt][nt], aH[mt], bL[nt]);
                    MMA_TF32(cacc[mt][nt], aL[mt], bH[nt]);
                }
        }

        if (t + 1 < nT) {
            stsm(1 - buf);
            __syncthreads();
        }
    }

    #pragma unroll
    for (int mt = 0; mt < 4; mt++) {
        #pragma unroll
        for (int nt = 0; nt < 4; nt++) {
            const int row0 = bm + m_base + mt * 16 + r;
            const int col  = bn + n_base + nt * 8 + 2 * cl4;
            float v0 = cacc[mt][nt][0], v1 = cacc[mt][nt][1];
            float v2 = cacc[mt][nt][2], v3 = cacc[mt][nt][3];
            if (bias) {
                const float bb0 = bias[col], bb1 = bias[col + 1];
                v0 += bb0; v1 += bb1; v2 += bb0; v3 += bb1;
            }
            float* p0 = &C[(size_t)row0 * N + col];
            float* p1 = &C[(size_t)(row0 + 8) * N + col];
            if (ACC) {
                float2 o0 = *(const float2*)p0;
                float2 o1 = *(const float2*)p1;
                v0 += o0.x; v1 += o0.y; v2 += o1.x; v3 += o1.y;
            }
            if (RELU) {
                v0 = fmaxf(v0, 0.f); v1 = fmaxf(v1, 0.f);
                v2 = fmaxf(v2, 0.f); v3 = fmaxf(v3, 0.f);
            }
            *(float2*)p0 = make_float2(v0, v1);
            *(float2*)p1 = make_float2(v2, v3);
        }
    }
}

// ============================================================================
// persistent TLSTM: all 256 steps in ONE kernel.
// Grid: 128 blocks = 8 j-tiles (32 cols) x 16 row-tiles (8 rows), 256 thr.
// Weights staged once in smem. Warp w reduces k-slice [w*32,w*32+32) for all
// 8 rows; smem tree reduction. Cross-block sync PER ROW-GROUP (8 blocks).
// ============================================================================
__device__ __forceinline__ float sigmoidf_(float x) { return 1.f / (1.f + __expf(-x)); }

__global__ __launch_bounds__(256, 1)
void tlstm_persistent(const float* __restrict__ u,    const float* __restrict__ ts,
                      const float* __restrict__ Wall, const float* __restrict__ bAll,
                      const float* __restrict__ Wd,   const float* __restrict__ bD,
                      float* h0b, float* c0b, float* h1b, float* c1b,
                      float* __restrict__ feat)
{
    extern __shared__ float sm[];
    float* ws  = sm;            // 32768 floats, [g][k/2][lane][2]
    float* wds = ws + 32768;    // 8192,  [k/2][lane][2]
    float* hs  = wds + 8192;    // 2048
    float* cs  = hs + 2048;     // 2048
    float* par = cs + 2048;     // 10240
    // total 55296 floats = 221184 bytes

    const int tid  = threadIdx.x;
    const int lane = tid & 31;
    const int wid  = tid >> 5;
    const int jt   = blockIdx.x & 7;
    const int rt   = blockIdx.x >> 3;
    const int j0   = jt * 32;
    const int r0   = rt * 8;
    const int j    = j0 + lane;
    const int brow = r0 + wid;

    // ---- stage weights once ----
    for (int idx = tid; idx < 4 * 256 * 32; idx += 256) {
        int g = idx >> 13;
        int k = (idx >> 5) & 255;
        int l = idx & 31;
        ws[g * 8192 + (k >> 1) * 64 + l * 2 + (k & 1)] = __ldg(&Wall[k * 1024 + g * 256 + j0 + l]);
    }
    for (int idx = tid; idx < 256 * 32; idx += 256) {
        int k = idx >> 5;
        int l = idx & 31;
        wds[(k >> 1) * 64 + l * 2 + (k & 1)] = __ldg(&Wd[k * 256 + j0 + l]);
    }
    const float b0 = bAll[j], b1 = bAll[j + 256], b2 = bAll[j + 512], b3 = bAll[j + 768];
    const float bd = bD[j];
    __syncthreads();

    for (int s = 0; s < S_SZ; s++) {
        const float* hprev = (s & 1) ? h1b : h0b;
        const float* cprev = (s & 1) ? c1b : c0b;
        float* hnew = (s & 1) ? h0b : h1b;
        float* cnew = (s & 1) ? c0b : c1b;

        // constant per-step operands: issue BEFORE the spin-wait so their DRAM
        // latency overlaps barrier latency (they don't depend on h/c).
        const float tt = ts[brow * S_SZ + s];
        const float* um = u + ((size_t)brow * S_SZ + s) * 1024;
        const float u0 = um[j], u1 = um[j + 256], u2 = um[j + 512], u3 = um[j + 768];

        if (s > 0) {
            if (tid == 0) {
                while (atomicAdd(&g_gen2[rt], 0u) < (unsigned)s) __nanosleep(32);
            }
            __syncthreads();
        }

        if (s == 0) {
            for (int i = tid; i < 512; i += 256) {
                *(float4*)&hs[i * 4] = make_float4(0.f, 0.f, 0.f, 0.f);
                *(float4*)&cs[i * 4] = make_float4(0.f, 0.f, 0.f, 0.f);
            }
        } else {
            for (int i = tid; i < 512; i += 256) {
                int e = i * 4;
                int rr = e >> 8;
                int cc = e & 255;
                *(float4*)&hs[e] = __ldcg((const float4*)&hprev[(r0 + rr) * 256 + cc]);
                *(float4*)&cs[e] = __ldcg((const float4*)&cprev[(r0 + rr) * 256 + cc]);
            }
        }
        __syncthreads();

        // ---- split-K mainloop: warp `wid` covers k in [wid*32, wid*32+32) ----
        float acc[8][5];
        #pragma unroll
        for (int rr = 0; rr < 8; rr++)
            #pragma unroll
            for (int g = 0; g < 5; g++) acc[rr][g] = 0.f;

        const int kb = wid * 32;
        #pragma unroll 2
        for (int k2 = 0; k2 < 16; k2++) {
            const int k  = kb + k2 * 2;
            const int wb = (k >> 1) * 64 + lane * 2;
            const float2 wdv = *(const float2*)&wds[wb];
            const float2 w0v = *(const float2*)&ws[wb];
            const float2 w1v = *(const float2*)&ws[8192  + wb];
            const float2 w2v = *(const float2*)&ws[16384 + wb];
            const float2 w3v = *(const float2*)&ws[24576 + wb];
            #pragma unroll
            for (int rr = 0; rr < 8; rr++) {
                const float2 h2 = *(const float2*)&hs[rr * 256 + k];
                const float2 c2 = *(const float2*)&cs[rr * 256 + k];
                acc[rr][0] += h2.x * w0v.x + h2.y * w0v.y;
                acc[rr][1] += h2.x * w1v.x + h2.y * w1v.y;
                acc[rr][2] += h2.x * w2v.x + h2.y * w2v.y;
                acc[rr][3] += h2.x * w3v.x + h2.y * w3v.y;
                acc[rr][4] += c2.x * wdv.x + c2.y * wdv.y;
            }
        }

        #pragma unroll
        for (int rr = 0; rr < 8; rr++)
            #pragma unroll
            for (int g = 0; g < 5; g++)
                par[((wid * 8 + rr) * 5 + g) * 32 + lane] = acc[rr][g];
        __syncthreads();

        // ---- reduce + gates: thread (wid=row, lane=col) owns one output ----
        float gv0 = 0.f, gv1 = 0.f, gv2 = 0.f, gv3 = 0.f, gv4 = 0.f;
        #pragma unroll
        for (int w = 0; w < 8; w++) {
            const int base = ((w * 8 + wid) * 5) * 32 + lane;
            gv0 += par[base];
            gv1 += par[base + 32];
            gv2 += par[base + 64];
            gv3 += par[base + 96];
            gv4 += par[base + 128];
        }

        const float cs1  = tanhf(gv4 + bd);
        const float cpv  = cs[wid * 256 + j];
        const float cadj = (cpv - cs1) + cs1 * tt;

        const float f  = sigmoidf_(gv0 + b0 + u0);
        const float ig = sigmoidf_(gv1 + b1 + u1);
        const float o  = sigmoidf_(gv2 + b2 + u2);
        const float ct = sigmoidf_(gv3 + b3 + u3);

        const float cn = f * cadj + ig * ct;
        const float hn = o * tanhf(cn);

        __stcg(&hnew[brow * 256 + j], hn);
        __stcg(&cnew[brow * 256 + j], cn);
        feat[((size_t)brow * S_SZ + s) * 256 + j] = hn;

        if (s < S_SZ - 1) {
            __threadfence();
            __syncthreads();
            if (tid == 0) {
                unsigned old = atomicAdd(&g_cnt2[rt], 1u);
                if (old == 7u) {
                    atomicExch(&g_cnt2[rt], 0u);
                    __threadfence();
                    atomicExch(&g_gen2[rt], (unsigned)(s + 1));   // release group
                }
            }
        }
    }
}

// ---------------- classifier ----------------
__global__ __launch_bounds__(256)
void cls_kernel(const float* __restrict__ feat, const float* __restrict__ w,
                const float* __restrict__ bb, float* __restrict__ out)
{
    const int warp = threadIdx.x >> 5;
    const int lane = threadIdx.x & 31;
    const int m = blockIdx.x * 8 + warp;
    const float* fr = feat + (size_t)m * 256;
    float s = 0.f;
    #pragma unroll
    for (int i = 0; i < 8; i++) s += fr[lane + 32 * i] * w[lane + 32 * i];
    #pragma unroll
    for (int off = 16; off; off >>= 1) s += __shfl_down_sync(0xffffffffu, s, off);
    if (lane == 0) out[m] = s + bb[0];
}

__global__ void init_kernel()
{
    int i = threadIdx.x;
    if (i < 16) { g_cnt2[i] = 0u; g_gen2[i] = 0u; }
}

// ---------------- launch ----------------
extern "C" void kernel_launch(void* const* d_in, const int* in_sizes, int n_in,
                              void* d_out, int out_size)
{
    const float* x      = (const float*)d_in[0];
    const float* stages = (const float*)d_in[1];
    const float* ts     = (const float*)d_in[2];
    const float* se_w1  = (const float*)d_in[3];
    const float* se_b1  = (const float*)d_in[4];
    const float* se_w2  = (const float*)d_in[5];
    const float* se_b2  = (const float*)d_in[6];
    const float* se_w3  = (const float*)d_in[7];
    const float* se_b3  = (const float*)d_in[8];
    const float* Wall   = (const float*)d_in[9];
    const float* bAll   = (const float*)d_in[10];
    const float* Uall   = (const float*)d_in[11];
    const float* bU     = (const float*)d_in[12];
    const float* Wd     = (const float*)d_in[13];
    const float* bD     = (const float*)d_in[14];
    const float* clsw   = (const float*)d_in[15];
    const float* clsb   = (const float*)d_in[16];

    float* out = (float*)d_out;

    float *st1, *st2, *st3, *u, *hb, *cb;
    cudaGetSymbolAddress((void**)&st1, g_st1);
    cudaGetSymbolAddress((void**)&st2, g_st2);
    cudaGetSymbolAddress((void**)&st3, g_st3);
    cudaGetSymbolAddress((void**)&u,   g_u);
    cudaGetSymbolAddress((void**)&hb,  g_h);
    cudaGetSymbolAddress((void**)&cb,  g_c);
    float* h0 = hb;  float* h1 = hb + B_SZ * HID;
    float* c0 = cb;  float* c1 = cb + B_SZ * HID;

    // feat: second output if harness exposes it, else scratch (st2 free by then)
    float* feat = (out_size >= MS + MS * HID) ? (out + MS) : st2;

    const int gemm_smem = 2 * 4 * TBUF * (int)sizeof(float);  // 69632 B
    cudaFuncSetAttribute(tf32_gemm<true,  false>,
                         cudaFuncAttributeMaxDynamicSharedMemorySize, gemm_smem);
    cudaFuncSetAttribute(tf32_gemm<false, false>,
                         cudaFuncAttributeMaxDynamicSharedMemorySize, gemm_smem);
    cudaFuncSetAttribute(tf32_gemm<false, true >,
                         cudaFuncAttributeMaxDynamicSharedMemorySize, gemm_smem);
    const int lstm_smem = 55296 * (int)sizeof(float);         // 221184 B
    cudaFuncSetAttribute(tlstm_persistent,
                         cudaFuncAttributeMaxDynamicSharedMemorySize, lstm_smem);

    init_kernel<<<1, 32>>>();

    // stage-embedding MLP (se1 fp32 due to K=67; se2/se3 on tensor cores)
    sgemm_kernel<true, false><<<dim3(2, MS / 128), 256>>>(stages, se_w1, se_b1, st1, MS, 256, 67);
    tf32_gemm<true, false><<<dim3(4, MS / 128), 256, gemm_smem>>>(st1, se_w2, se_b2, st2, MS, 512, 256);
    tf32_gemm<true, false><<<dim3(8, MS / 128), 256, gemm_smem>>>(st2, se_w3, se_b3, st3, MS, 1024, 512);

    // u = x @ U[0:1024] + bU ; u += st3 @ U[1024:2048]  (concat avoided)
    tf32_gemm<false, false><<<dim3(8, MS / 128), 256, gemm_smem>>>(x,   Uall,               bU,      u, MS, 1024, 1024);
    tf32_gemm<false, true ><<<dim3(8, MS / 128), 256, gemm_smem>>>(st3, Uall + 1024 * 1024, nullptr, u, MS, 1024, 1024);

    // all 256 TLSTM steps in one persistent kernel
    tlstm_persistent<<<NBLK, 256, lstm_smem>>>(u, ts, Wall, bAll, Wd, bD,
                                               h0, c0, h1, c1, feat);

    // classifier
    cls_kernel<<<MS / 8, 256>>>(feat, clsw, clsb, out);
}

// round 8
// speedup vs baseline: 1.3360x; 1.3360x over previous
#include <cuda_runtime.h>
#include <cuda_bf16.h>
#include <math.h>
#include <stdint.h>
#include <string.h>

#define B_SZ 128
#define S_SZ 256
#define HID  256
#define MS   (B_SZ * S_SZ)   // 32768 rows
#define NBLK 128             // persistent LSTM grid (<=148 SMs -> all resident)

// ---------------- scratch (device globals; no allocation allowed) ----------------
__device__ float g_st1[MS * 256];
__device__ float g_st2[MS * 512];
__device__ float g_st3[MS * 1024];
__device__ float g_u  [MS * 1024];
__device__ float g_h  [2 * B_SZ * HID];
__device__ float g_c  [2 * B_SZ * HID];
__device__ unsigned g_cnt2[16];
__device__ unsigned g_gen2[16];

// ============================================================================
// fp32 SGEMM (used only for se1, K=67): BM=128,BN=128,BK=8, double-buffered.
// ============================================================================
template<bool RELU, bool ACC>
__global__ __launch_bounds__(256, 2)
void sgemm_kernel(const float* __restrict__ A, const float* __restrict__ Bm,
                  const float* __restrict__ bias, float* __restrict__ C,
                  int M, int N, int K)
{
    __shared__ float As[2][8][128];
    __shared__ float Bs[2][8][128];

    const int tid = threadIdx.x;
    const int tx  = tid & 15;
    const int ty  = tid >> 4;
    const int bm  = blockIdx.y * 128;
    const int bn  = blockIdx.x * 128;

    float acc[8][8] = {};

    const int a_base = tid * 4;
    const int am = a_base >> 3;
    const int ak = a_base & 7;
    const int bk = tid >> 5;
    const int bn4 = (tid & 31) * 4;

    float ra[4];
    float4 rb;

    auto ldreg = [&](int k0) {
        #pragma unroll
        for (int i = 0; i < 4; i++) {
            int gk = k0 + ak + i;
            ra[i] = (gk < K) ? A[(size_t)(bm + am) * K + gk] : 0.f;
        }
        if (k0 + bk < K) rb = *(const float4*)&Bm[(size_t)(k0 + bk) * N + bn + bn4];
        else             rb = make_float4(0.f, 0.f, 0.f, 0.f);
    };
    auto stsm = [&](int buf) {
        #pragma unroll
        for (int i = 0; i < 4; i++) As[buf][ak + i][am] = ra[i];
        *(float4*)&Bs[buf][bk][bn4] = rb;
    };

    ldreg(0);
    stsm(0);
    __syncthreads();

    const int nT = (K + 7) / 8;
    for (int t = 0; t < nT; t++) {
        const int buf = t & 1;
        if (t + 1 < nT) ldreg((t + 1) * 8);

        #pragma unroll
        for (int kk = 0; kk < 8; kk++) {
            float4 a0 = *(const float4*)&As[buf][kk][ty * 8];
            float4 a1 = *(const float4*)&As[buf][kk][ty * 8 + 4];
            float4 b0 = *(const float4*)&Bs[buf][kk][tx * 8];
            float4 b1 = *(const float4*)&Bs[buf][kk][tx * 8 + 4];
            float av[8] = {a0.x, a0.y, a0.z, a0.w, a1.x, a1.y, a1.z, a1.w};
            float bv[8] = {b0.x, b0.y, b0.z, b0.w, b1.x, b1.y, b1.z, b1.w};
            #pragma unroll
            for (int i = 0; i < 8; i++)
                #pragma unroll
                for (int j = 0; j < 8; j++)
                    acc[i][j] += av[i] * bv[j];
        }

        if (t + 1 < nT) {
            stsm(1 - buf);
            __syncthreads();
        }
    }

    #pragma unroll
    for (int i = 0; i < 8; i++) {
        const size_t row = (size_t)(bm + ty * 8 + i);
        #pragma unroll
        for (int j = 0; j < 8; j += 4) {
            const int col = bn + tx * 8 + j;
            float4 v = make_float4(acc[i][j], acc[i][j + 1], acc[i][j + 2], acc[i][j + 3]);
            if (bias) {
                v.x += bias[col];     v.y += bias[col + 1];
                v.z += bias[col + 2]; v.w += bias[col + 3];
            }
            if (ACC) {
                float4 o = *(const float4*)&C[row * N + col];
                v.x += o.x; v.y += o.y; v.z += o.z; v.w += o.w;
            }
            if (RELU) {
                v.x = fmaxf(v.x, 0.f); v.y = fmaxf(v.y, 0.f);
                v.z = fmaxf(v.z, 0.f); v.w = fmaxf(v.w, 0.f);
            }
            *(float4*)&C[row * N + col] = v;
        }
    }
}

// ============================================================================
// split-bf16 tensor-core GEMM: C = act(A[M,K] @ B[K,N] + bias (+C))
// a = aH + aL (bf16 each); D += aH*bH + aH*bL + aL*bH  (residual ~2^-16 rel).
// BM=128, BN=128, BK=32 (16 k-pairs). 256 threads = 8 warps (2x4), warp tile
// 64x32 via m16n8k16. Smem holds k-pair-packed u32 (lo16 = even k).
// Requires K%32==0, N%128==0, M%128==0.
// ============================================================================
#define PSTR 136                      // smem pair-row stride (u32): conflict-free
#define PBUF 2176                     // 16 pair-rows * PSTR per matrix per buffer

__device__ __forceinline__ uint32_t packbf2(float x, float y) {
    __nv_bfloat162 t = __floats2bfloat162_rn(x, y);   // x -> low 16, y -> high 16
    uint32_t r; memcpy(&r, &t, 4); return r;
}

#define MMA_BF16(cc, aa, bb)                                                   \
    asm volatile("mma.sync.aligned.m16n8k16.row.col.f32.bf16.bf16.f32 "        \
        "{%0,%1,%2,%3}, {%4,%5,%6,%7}, {%8,%9}, {%0,%1,%2,%3};"                \
        : "+f"((cc)[0]), "+f"((cc)[1]), "+f"((cc)[2]), "+f"((cc)[3])           \
        : "r"((aa)[0]), "r"((aa)[1]), "r"((aa)[2]), "r"((aa)[3]),              \
          "r"((bb)[0]), "r"((bb)[1]))

template<bool RELU, bool ACC>
__global__ __launch_bounds__(256, 1)
void bf16_gemm(const float* __restrict__ A, const float* __restrict__ Bm,
               const float* __restrict__ bias, float* __restrict__ C,
               int M, int N, int K)
{
    extern __shared__ uint32_t smx[];
    // per buffer: [APH | APL | BPH | BPL], each PBUF u32, layout [kpair][m]/[kpair][n]
    const int tid  = threadIdx.x;
    const int lane = tid & 31;
    const int wid  = tid >> 5;
    const int wm   = wid >> 2;            // 0..1
    const int wn   = wid & 3;             // 0..3
    const int r    = lane >> 2;           // groupID 0..7
    const int cl4  = lane & 3;            // threadID_in_group 0..3
    const int bm   = blockIdx.y * 128;
    const int bn   = blockIdx.x * 128;
    const int m_base = wm * 64;
    const int n_base = wn * 32;

    // loader mapping: A: 128 rows x 32 k; thread -> (row tid>>1, k-seg 16)
    const int la_m   = tid >> 1;
    const int la_kp0 = (tid & 1) * 8;     // pair base 0 or 8
    // B: 16 pair-rows x 128 n; thread -> (pair tid>>4, 8 cols)
    const int lb_kp  = tid >> 4;          // 0..15
    const int lb_n   = (tid & 15) * 8;

    float4 ra[4];                         // A: 16 consecutive k floats
    float4 rb0[2], rb1[2];                // B: rows 2kp, 2kp+1, 8 cols each

    auto ldreg = [&](int k0) {
        const float* ap = A + (size_t)(bm + la_m) * K + k0 + la_kp0 * 2;
        #pragma unroll
        for (int i = 0; i < 4; i++) ra[i] = *(const float4*)(ap + 4 * i);
        const float* bp = Bm + (size_t)(k0 + 2 * lb_kp) * N + bn + lb_n;
        rb0[0] = *(const float4*)bp;       rb0[1] = *(const float4*)(bp + 4);
        rb1[0] = *(const float4*)(bp + N); rb1[1] = *(const float4*)(bp + N + 4);
    };
    auto stsm = [&](int buf) {
        uint32_t* APH = smx + buf * 4 * PBUF;
        uint32_t* APL = APH + PBUF;
        uint32_t* BPH = APL + PBUF;
        uint32_t* BPL = BPH + PBUF;
        const float* av = (const float*)ra;
        #pragma unroll
        for (int i = 0; i < 8; i++) {
            float x = av[2 * i], y = av[2 * i + 1];
            uint32_t ph = packbf2(x, y);
            float hx = __uint_as_float(ph << 16);
            float hy = __uint_as_float(ph & 0xffff0000u);
            APH[(la_kp0 + i) * PSTR + la_m] = ph;
            APL[(la_kp0 + i) * PSTR + la_m] = packbf2(x - hx, y - hy);
        }
        const float* b0 = (const float*)rb0;
        const float* b1 = (const float*)rb1;
        #pragma unroll
        for (int i = 0; i < 8; i++) {
            float x = b0[i], y = b1[i];          // k even, k odd at col lb_n+i
            uint32_t ph = packbf2(x, y);
            float hx = __uint_as_float(ph << 16);
            float hy = __uint_as_float(ph & 0xffff0000u);
            BPH[lb_kp * PSTR + lb_n + i] = ph;
            BPL[lb_kp * PSTR + lb_n + i] = packbf2(x - hx, y - hy);
        }
    };

    float cacc[4][4][4] = {};

    ldreg(0);
    stsm(0);
    __syncthreads();

    const int nT = K / 32;
    for (int t = 0; t < nT; t++) {
        const int buf = t & 1;
        if (t + 1 < nT) ldreg((t + 1) * 32);

        const uint32_t* APH = smx + buf * 4 * PBUF;
        const uint32_t* APL = APH + PBUF;
        const uint32_t* BPH = APL + PBUF;
        const uint32_t* BPL = BPH + PBUF;

        #pragma unroll
        for (int kk = 0; kk < 2; kk++) {
            const int base0 = (kk * 8 + cl4) * PSTR;       // pair cl4   (k16 low half)
            const int base4 = (kk * 8 + cl4 + 4) * PSTR;   // pair cl4+4 (k16 high half)
            uint32_t aH[4][4], aL[4][4], bH[4][2], bL[4][2];
            #pragma unroll
            for (int mt = 0; mt < 4; mt++) {
                const int rl = m_base + mt * 16 + r;
                aH[mt][0] = APH[base0 + rl];     aH[mt][1] = APH[base0 + rl + 8];
                aH[mt][2] = APH[base4 + rl];     aH[mt][3] = APH[base4 + rl + 8];
                aL[mt][0] = APL[base0 + rl];     aL[mt][1] = APL[base0 + rl + 8];
                aL[mt][2] = APL[base4 + rl];     aL[mt][3] = APL[base4 + rl + 8];
            }
            #pragma unroll
            for (int nt = 0; nt < 4; nt++) {
                const int cc = n_base + nt * 8 + r;
                bH[nt][0] = BPH[base0 + cc];     bH[nt][1] = BPH[base4 + cc];
                bL[nt][0] = BPL[base0 + cc];     bL[nt][1] = BPL[base4 + cc];
            }
            #pragma unroll
            for (int mt = 0; mt < 4; mt++)
                #pragma unroll
                for (int nt = 0; nt < 4; nt++) {
                    MMA_BF16(cacc[mt][nt], aH[mt], bH[nt]);
                    MMA_BF16(cacc[mt][nt], aH[mt], bL[nt]);
                    MMA_BF16(cacc[mt][nt], aL[mt], bH[nt]);
                }
        }

        if (t + 1 < nT) {
            stsm(1 - buf);
            __syncthreads();
        }
    }

    // epilogue: c0/c1 at (row0, col,col+1); c2/c3 at (row0+8, ...)
    #pragma unroll
    for (int mt = 0; mt < 4; mt++) {
        #pragma unroll
        for (int nt = 0; nt < 4; nt++) {
            const int row0 = bm + m_base + mt * 16 + r;
            const int col  = bn + n_base + nt * 8 + 2 * cl4;
            float v0 = cacc[mt][nt][0], v1 = cacc[mt][nt][1];
            float v2 = cacc[mt][nt][2], v3 = cacc[mt][nt][3];
            if (bias) {
                const float bb0 = bias[col], bb1 = bias[col + 1];
                v0 += bb0; v1 += bb1; v2 += bb0; v3 += bb1;
            }
            float* p0 = &C[(size_t)row0 * N + col];
            float* p1 = &C[(size_t)(row0 + 8) * N + col];
            if (ACC) {
                float2 o0 = *(const float2*)p0;
                float2 o1 = *(const float2*)p1;
                v0 += o0.x; v1 += o0.y; v2 += o1.x; v3 += o1.y;
            }
            if (RELU) {
                v0 = fmaxf(v0, 0.f); v1 = fmaxf(v1, 0.f);
                v2 = fmaxf(v2, 0.f); v3 = fmaxf(v3, 0.f);
            }
            *(float2*)p0 = make_float2(v0, v1);
            *(float2*)p1 = make_float2(v2, v3);
        }
    }
}

// ============================================================================
// persistent TLSTM: all 256 steps in ONE kernel (unchanged from passing R5).
// ============================================================================
__device__ __forceinline__ float sigmoidf_(float x) { return 1.f / (1.f + __expf(-x)); }

__global__ __launch_bounds__(256, 1)
void tlstm_persistent(const float* __restrict__ u,    const float* __restrict__ ts,
                      const float* __restrict__ Wall, const float* __restrict__ bAll,
                      const float* __restrict__ Wd,   const float* __restrict__ bD,
                      float* h0b, float* c0b, float* h1b, float* c1b,
                      float* __restrict__ feat)
{
    extern __shared__ float sm[];
    float* ws  = sm;            // 32768 floats, [g][k/2][lane][2]
    float* wds = ws + 32768;    // 8192,  [k/2][lane][2]
    float* hs  = wds + 8192;    // 2048
    float* cs  = hs + 2048;     // 2048
    float* par = cs + 2048;     // 10240
    // total 55296 floats = 221184 bytes

    const int tid  = threadIdx.x;
    const int lane = tid & 31;
    const int wid  = tid >> 5;
    const int jt   = blockIdx.x & 7;
    const int rt   = blockIdx.x >> 3;
    const int j0   = jt * 32;
    const int r0   = rt * 8;
    const int j    = j0 + lane;
    const int brow = r0 + wid;

    for (int idx = tid; idx < 4 * 256 * 32; idx += 256) {
        int g = idx >> 13;
        int k = (idx >> 5) & 255;
        int l = idx & 31;
        ws[g * 8192 + (k >> 1) * 64 + l * 2 + (k & 1)] = __ldg(&Wall[k * 1024 + g * 256 + j0 + l]);
    }
    for (int idx = tid; idx < 256 * 32; idx += 256) {
        int k = idx >> 5;
        int l = idx & 31;
        wds[(k >> 1) * 64 + l * 2 + (k & 1)] = __ldg(&Wd[k * 256 + j0 + l]);
    }
    const float b0 = bAll[j], b1 = bAll[j + 256], b2 = bAll[j + 512], b3 = bAll[j + 768];
    const float bd = bD[j];
    __syncthreads();

    for (int s = 0; s < S_SZ; s++) {
        const float* hprev = (s & 1) ? h1b : h0b;
        const float* cprev = (s & 1) ? c1b : c0b;
        float* hnew = (s & 1) ? h0b : h1b;
        float* cnew = (s & 1) ? c0b : c1b;

        // constant per-step operands BEFORE the spin: DRAM latency overlaps barrier
        const float tt = ts[brow * S_SZ + s];
        const float* um = u + ((size_t)brow * S_SZ + s) * 1024;
        const float u0 = um[j], u1 = um[j + 256], u2 = um[j + 512], u3 = um[j + 768];

        if (s > 0) {
            if (tid == 0) {
                while (atomicAdd(&g_gen2[rt], 0u) < (unsigned)s) __nanosleep(32);
            }
            __syncthreads();
        }

        if (s == 0) {
            for (int i = tid; i < 512; i += 256) {
                *(float4*)&hs[i * 4] = make_float4(0.f, 0.f, 0.f, 0.f);
                *(float4*)&cs[i * 4] = make_float4(0.f, 0.f, 0.f, 0.f);
            }
        } else {
            for (int i = tid; i < 512; i += 256) {
                int e = i * 4;
                int rr = e >> 8;
                int cc = e & 255;
                *(float4*)&hs[e] = __ldcg((const float4*)&hprev[(r0 + rr) * 256 + cc]);
                *(float4*)&cs[e] = __ldcg((const float4*)&cprev[(r0 + rr) * 256 + cc]);
            }
        }
        __syncthreads();

        float acc[8][5];
        #pragma unroll
        for (int rr = 0; rr < 8; rr++)
            #pragma unroll
            for (int g = 0; g < 5; g++) acc[rr][g] = 0.f;

        const int kb = wid * 32;
        #pragma unroll 2
        for (int k2 = 0; k2 < 16; k2++) {
            const int k  = kb + k2 * 2;
            const int wb = (k >> 1) * 64 + lane * 2;
            const float2 wdv = *(const float2*)&wds[wb];
            const float2 w0v = *(const float2*)&ws[wb];
            const float2 w1v = *(const float2*)&ws[8192  + wb];
            const float2 w2v = *(const float2*)&ws[16384 + wb];
            const float2 w3v = *(const float2*)&ws[24576 + wb];
            #pragma unroll
            for (int rr = 0; rr < 8; rr++) {
                const float2 h2 = *(const float2*)&hs[rr * 256 + k];
                const float2 c2 = *(const float2*)&cs[rr * 256 + k];
                acc[rr][0] += h2.x * w0v.x + h2.y * w0v.y;
                acc[rr][1] += h2.x * w1v.x + h2.y * w1v.y;
                acc[rr][2] += h2.x * w2v.x + h2.y * w2v.y;
                acc[rr][3] += h2.x * w3v.x + h2.y * w3v.y;
                acc[rr][4] += c2.x * wdv.x + c2.y * wdv.y;
            }
        }

        #pragma unroll
        for (int rr = 0; rr < 8; rr++)
            #pragma unroll
            for (int g = 0; g < 5; g++)
                par[((wid * 8 + rr) * 5 + g) * 32 + lane] = acc[rr][g];
        __syncthreads();

        float gv0 = 0.f, gv1 = 0.f, gv2 = 0.f, gv3 = 0.f, gv4 = 0.f;
        #pragma unroll
        for (int w = 0; w < 8; w++) {
            const int base = ((w * 8 + wid) * 5) * 32 + lane;
            gv0 += par[base];
            gv1 += par[base + 32];
            gv2 += par[base + 64];
            gv3 += par[base + 96];
            gv4 += par[base + 128];
        }

        const float cs1  = tanhf(gv4 + bd);
        const float cpv  = cs[wid * 256 + j];
        const float cadj = (cpv - cs1) + cs1 * tt;

        const float f  = sigmoidf_(gv0 + b0 + u0);
        const float ig = sigmoidf_(gv1 + b1 + u1);
        const float o  = sigmoidf_(gv2 + b2 + u2);
        const float ct = sigmoidf_(gv3 + b3 + u3);

        const float cn = f * cadj + ig * ct;
        const float hn = o * tanhf(cn);

        __stcg(&hnew[brow * 256 + j], hn);
        __stcg(&cnew[brow * 256 + j], cn);
        feat[((size_t)brow * S_SZ + s) * 256 + j] = hn;

        if (s < S_SZ - 1) {
            __threadfence();
            __syncthreads();
            if (tid == 0) {
                unsigned old = atomicAdd(&g_cnt2[rt], 1u);
                if (old == 7u) {
                    atomicExch(&g_cnt2[rt], 0u);
                    __threadfence();
                    atomicExch(&g_gen2[rt], (unsigned)(s + 1));
                }
            }
        }
    }
}

// ---------------- classifier ----------------
__global__ __launch_bounds__(256)
void cls_kernel(const float* __restrict__ feat, const float* __restrict__ w,
                const float* __restrict__ bb, float* __restrict__ out)
{
    const int warp = threadIdx.x >> 5;
    const int lane = threadIdx.x & 31;
    const int m = blockIdx.x * 8 + warp;
    const float* fr = feat + (size_t)m * 256;
    float s = 0.f;
    #pragma unroll
    for (int i = 0; i < 8; i++) s += fr[lane + 32 * i] * w[lane + 32 * i];
    #pragma unroll
    for (int off = 16; off; off >>= 1) s += __shfl_down_sync(0xffffffffu, s, off);
    if (lane == 0) out[m] = s + bb[0];
}

__global__ void init_kernel()
{
    int i = threadIdx.x;
    if (i < 16) { g_cnt2[i] = 0u; g_gen2[i] = 0u; }
}

// ---------------- launch ----------------
extern "C" void kernel_launch(void* const* d_in, const int* in_sizes, int n_in,
                              void* d_out, int out_size)
{
    const float* x      = (const float*)d_in[0];
    const float* stages = (const float*)d_in[1];
    const float* ts     = (const float*)d_in[2];
    const float* se_w1  = (const float*)d_in[3];
    const float* se_b1  = (const float*)d_in[4];
    const float* se_w2  = (const float*)d_in[5];
    const float* se_b2  = (const float*)d_in[6];
    const float* se_w3  = (const float*)d_in[7];
    const float* se_b3  = (const float*)d_in[8];
    const float* Wall   = (const float*)d_in[9];
    const float* bAll   = (const float*)d_in[10];
    const float* Uall   = (const float*)d_in[11];
    const float* bU     = (const float*)d_in[12];
    const float* Wd     = (const float*)d_in[13];
    const float* bD     = (const float*)d_in[14];
    const float* clsw   = (const float*)d_in[15];
    const float* clsb   = (const float*)d_in[16];

    float* out = (float*)d_out;

    float *st1, *st2, *st3, *u, *hb, *cb;
    cudaGetSymbolAddress((void**)&st1, g_st1);
    cudaGetSymbolAddress((void**)&st2, g_st2);
    cudaGetSymbolAddress((void**)&st3, g_st3);
    cudaGetSymbolAddress((void**)&u,   g_u);
    cudaGetSymbolAddress((void**)&hb,  g_h);
    cudaGetSymbolAddress((void**)&cb,  g_c);
    float* h0 = hb;  float* h1 = hb + B_SZ * HID;
    float* c0 = cb;  float* c1 = cb + B_SZ * HID;

    float* feat = (out_size >= MS + MS * HID) ? (out + MS) : st2;

    const int gemm_smem = 2 * 4 * PBUF * (int)sizeof(uint32_t);  // 69632 B
    cudaFuncSetAttribute(bf16_gemm<true,  false>,
                         cudaFuncAttributeMaxDynamicSharedMemorySize, gemm_smem);
    cudaFuncSetAttribute(bf16_gemm<false, false>,
                         cudaFuncAttributeMaxDynamicSharedMemorySize, gemm_smem);
    cudaFuncSetAttribute(bf16_gemm<false, true >,
                         cudaFuncAttributeMaxDynamicSharedMemorySize, gemm_smem);
    const int lstm_smem = 55296 * (int)sizeof(float);            // 221184 B
    cudaFuncSetAttribute(tlstm_persistent,
                         cudaFuncAttributeMaxDynamicSharedMemorySize, lstm_smem);

    init_kernel<<<1, 32>>>();

    // stage-embedding MLP (se1 fp32 due to K=67; se2/se3 on tensor cores)
    sgemm_kernel<true, false><<<dim3(2, MS / 128), 256>>>(stages, se_w1, se_b1, st1, MS, 256, 67);
    bf16_gemm<true, false><<<dim3(4, MS / 128), 256, gemm_smem>>>(st1, se_w2, se_b2, st2, MS, 512, 256);
    bf16_gemm<true, false><<<dim3(8, MS / 128), 256, gemm_smem>>>(st2, se_w3, se_b3, st3, MS, 1024, 512);

    // u = x @ U[0:1024] + bU ; u += st3 @ U[1024:2048]  (concat avoided)
    bf16_gemm<false, false><<<dim3(8, MS / 128), 256, gemm_smem>>>(x,   Uall,               bU,      u, MS, 1024, 1024);
    bf16_gemm<false, true ><<<dim3(8, MS / 128), 256, gemm_smem>>>(st3, Uall + 1024 * 1024, nullptr, u, MS, 1024, 1024);

    // all 256 TLSTM steps in one persistent kernel
    tlstm_persistent<<<NBLK, 256, lstm_smem>>>(u, ts, Wall, bAll, Wd, bD,
                                               h0, c0, h1, c1, feat);

    // classifier
    cls_kernel<<<MS / 8, 256>>>(feat, clsw, clsb, out);
}

// round 10
// speedup vs baseline: 1.4686x; 1.0993x over previous
#include <cuda_runtime.h>
#include <cuda_bf16.h>
#include <math.h>
#include <stdint.h>
#include <string.h>

#define B_SZ 128
#define S_SZ 256
#define HID  256
#define MS   (B_SZ * S_SZ)   // 32768 rows
#define NBLK 128             // persistent LSTM grid (<=148 SMs -> all resident)

// ---------------- scratch (device globals; no allocation allowed) ----------------
__device__ float g_st1[MS * 256];
__device__ float g_st2[MS * 512];
__device__ float g_st3[MS * 1024];
__device__ float g_u  [MS * 1024];
__device__ float g_h  [2 * B_SZ * HID];
__device__ float g_c  [2 * B_SZ * HID];
__device__ unsigned g_cnt2[16];
__device__ unsigned g_gen2[16];

// ============================================================================
// fp32 SGEMM (used only for se1, K=67): BM=128,BN=128,BK=8, double-buffered.
// ============================================================================
template<bool RELU, bool ACC>
__global__ __launch_bounds__(256, 2)
void sgemm_kernel(const float* __restrict__ A, const float* __restrict__ Bm,
                  const float* __restrict__ bias, float* __restrict__ C,
                  int M, int N, int K)
{
    __shared__ float As[2][8][128];
    __shared__ float Bs[2][8][128];

    const int tid = threadIdx.x;
    const int tx  = tid & 15;
    const int ty  = tid >> 4;
    const int bm  = blockIdx.y * 128;
    const int bn  = blockIdx.x * 128;

    float acc[8][8] = {};

    const int a_base = tid * 4;
    const int am = a_base >> 3;
    const int ak = a_base & 7;
    const int bk = tid >> 5;
    const int bn4 = (tid & 31) * 4;

    float ra[4];
    float4 rb;

    auto ldreg = [&](int k0) {
        #pragma unroll
        for (int i = 0; i < 4; i++) {
            int gk = k0 + ak + i;
            ra[i] = (gk < K) ? A[(size_t)(bm + am) * K + gk] : 0.f;
        }
        if (k0 + bk < K) rb = *(const float4*)&Bm[(size_t)(k0 + bk) * N + bn + bn4];
        else             rb = make_float4(0.f, 0.f, 0.f, 0.f);
    };
    auto stsm = [&](int buf) {
        #pragma unroll
        for (int i = 0; i < 4; i++) As[buf][ak + i][am] = ra[i];
        *(float4*)&Bs[buf][bk][bn4] = rb;
    };

    ldreg(0);
    stsm(0);
    __syncthreads();

    const int nT = (K + 7) / 8;
    for (int t = 0; t < nT; t++) {
        const int buf = t & 1;
        if (t + 1 < nT) ldreg((t + 1) * 8);

        #pragma unroll
        for (int kk = 0; kk < 8; kk++) {
            float4 a0 = *(const float4*)&As[buf][kk][ty * 8];
            float4 a1 = *(const float4*)&As[buf][kk][ty * 8 + 4];
            float4 b0 = *(const float4*)&Bs[buf][kk][tx * 8];
            float4 b1 = *(const float4*)&Bs[buf][kk][tx * 8 + 4];
            float av[8] = {a0.x, a0.y, a0.z, a0.w, a1.x, a1.y, a1.z, a1.w};
            float bv[8] = {b0.x, b0.y, b0.z, b0.w, b1.x, b1.y, b1.z, b1.w};
            #pragma unroll
            for (int i = 0; i < 8; i++)
                #pragma unroll
                for (int j = 0; j < 8; j++)
                    acc[i][j] += av[i] * bv[j];
        }

        if (t + 1 < nT) {
            stsm(1 - buf);
            __syncthreads();
        }
    }

    #pragma unroll
    for (int i = 0; i < 8; i++) {
        const size_t row = (size_t)(bm + ty * 8 + i);
        #pragma unroll
        for (int j = 0; j < 8; j += 4) {
            const int col = bn + tx * 8 + j;
            float4 v = make_float4(acc[i][j], acc[i][j + 1], acc[i][j + 2], acc[i][j + 3]);
            if (bias) {
                v.x += bias[col];     v.y += bias[col + 1];
                v.z += bias[col + 2]; v.w += bias[col + 3];
            }
            if (ACC) {
                float4 o = *(const float4*)&C[row * N + col];
                v.x += o.x; v.y += o.y; v.z += o.z; v.w += o.w;
            }
            if (RELU) {
                v.x = fmaxf(v.x, 0.f); v.y = fmaxf(v.y, 0.f);
                v.z = fmaxf(v.z, 0.f); v.w = fmaxf(v.w, 0.f);
            }
            *(float4*)&C[row * N + col] = v;
        }
    }
}

// ============================================================================
// split-bf16 tensor-core GEMM with ldmatrix A-fragments.
// C = act(A[M,K] @ B[K,N] + bias (+C)); a = aH + aL; D += aH bH + aH bL + aL bH.
// BM=128, BN=128, BK=32. 8 warps (2x4), warp tile 64x32 via m16n8k16.
// A smem: [m][kpair] row stride 20 u32 (ldmatrix-friendly, conflict-free).
// B smem: [kpair][n] stride 136 u32 (scalar LDS, conflict-free).
// Requires K%32==0, N%128==0, M%128==0.
// ============================================================================
#define ASTR 20                       // A row stride in u32 (16 used + 4 pad)
#define ABUF 2560                     // 128 rows * ASTR
#define PSTR 136                      // B pair-row stride (u32)
#define PBUF 2176                     // 16 pair-rows * PSTR
#define GBUF 9472                     // ABUF*2 + PBUF*2 per stage
// stage layout: [AH(2560) | AL(2560) | BH(2176) | BL(2176)]

__device__ __forceinline__ uint32_t packbf2(float x, float y) {
    __nv_bfloat162 t = __floats2bfloat162_rn(x, y);   // x -> low 16, y -> high 16
    uint32_t r; memcpy(&r, &t, 4); return r;
}

#define MMA_BF16(cc, aa, bb)                                                   \
    asm volatile("mma.sync.aligned.m16n8k16.row.col.f32.bf16.bf16.f32 "        \
        "{%0,%1,%2,%3}, {%4,%5,%6,%7}, {%8,%9}, {%0,%1,%2,%3};"                \
        : "+f"((cc)[0]), "+f"((cc)[1]), "+f"((cc)[2]), "+f"((cc)[3])           \
        : "r"((aa)[0]), "r"((aa)[1]), "r"((aa)[2]), "r"((aa)[3]),              \
          "r"((bb)[0]), "r"((bb)[1]))

#define LDSM_X4(rr0, rr1, rr2, rr3, saddr)                                     \
    asm volatile("ldmatrix.sync.aligned.m8n8.x4.shared.b16 {%0,%1,%2,%3}, [%4];" \
        : "=r"(rr0), "=r"(rr1), "=r"(rr2), "=r"(rr3) : "r"(saddr))

template<bool RELU, bool ACC>
__global__ __launch_bounds__(256, 1)
void bf16_gemm(const float* __restrict__ A, const float* __restrict__ Bm,
               const float* __restrict__ bias, float* __restrict__ C,
               int M, int N, int K)
{
    extern __shared__ uint32_t smx[];
    const int tid  = threadIdx.x;
    const int lane = tid & 31;
    const int wid  = tid >> 5;
    const int wm   = wid >> 2;            // 0..1
    const int wn   = wid & 3;             // 0..3
    const int r    = lane >> 2;           // groupID 0..7
    const int cl4  = lane & 3;            // threadID_in_group 0..3
    const int bm   = blockIdx.y * 128;
    const int bn   = blockIdx.x * 128;
    const int m_base = wm * 64;
    const int n_base = wn * 32;

    const uint32_t smem_sh = (uint32_t)__cvta_generic_to_shared(smx);
    // ldmatrix lane addressing for A 16x16 tiles:
    // lanes 0-15 -> rows (lane&15), lanes 16-31 -> same rows, k-pair offset +4
    const int a_row_in_tile = lane & 15;
    const int a_kp_half     = (lane >> 4) * 4;

    // loader mapping: A: thread -> (row tid>>1, 16 consecutive k = 8 pairs)
    const int la_m   = tid >> 1;
    const int la_kp0 = (tid & 1) * 8;     // pair base 0 or 8
    // B: 16 pair-rows x 128 n; thread -> (pair tid>>4, 8 cols)
    const int lb_kp  = tid >> 4;          // 0..15
    const int lb_n   = (tid & 15) * 8;

    float4 ra[4];                         // A: 16 consecutive k floats
    float4 rb0[2], rb1[2];                // B: rows 2kp, 2kp+1, 8 cols each

    auto ldreg = [&](int k0) {
        const float* ap = A + (size_t)(bm + la_m) * K + k0 + la_kp0 * 2;
        #pragma unroll
        for (int i = 0; i < 4; i++) ra[i] = *(const float4*)(ap + 4 * i);
        const float* bp = Bm + (size_t)(k0 + 2 * lb_kp) * N + bn + lb_n;
        rb0[0] = *(const float4*)bp;       rb0[1] = *(const float4*)(bp + 4);
        rb1[0] = *(const float4*)(bp + N); rb1[1] = *(const float4*)(bp + N + 4);
    };
    auto stsm = [&](int buf) {
        uint32_t* AH = smx + buf * GBUF;
        uint32_t* AL = AH + ABUF;
        uint32_t* BH = smx + buf * GBUF + 2 * ABUF;
        uint32_t* BL = BH + PBUF;
        const float* av = (const float*)ra;
        uint32_t ph[8], pl[8];
        #pragma unroll
        for (int i = 0; i < 8; i++) {
            float x = av[2 * i], y = av[2 * i + 1];
            ph[i] = packbf2(x, y);
            float hx = __uint_as_float(ph[i] << 16);
            float hy = __uint_as_float(ph[i] & 0xffff0000u);
            pl[i] = packbf2(x - hx, y - hy);
        }
        const int abase = la_m * ASTR + la_kp0;
        *(uint4*)&AH[abase]     = make_uint4(ph[0], ph[1], ph[2], ph[3]);
        *(uint4*)&AH[abase + 4] = make_uint4(ph[4], ph[5], ph[6], ph[7]);
        *(uint4*)&AL[abase]     = make_uint4(pl[0], pl[1], pl[2], pl[3]);
        *(uint4*)&AL[abase + 4] = make_uint4(pl[4], pl[5], pl[6], pl[7]);
        const float* b0 = (const float*)rb0;
        const float* b1 = (const float*)rb1;
        #pragma unroll
        for (int i = 0; i < 8; i++) {
            float x = b0[i], y = b1[i];          // k even, k odd at col lb_n+i
            uint32_t bh = packbf2(x, y);
            float hx = __uint_as_float(bh << 16);
            float hy = __uint_as_float(bh & 0xffff0000u);
            BH[lb_kp * PSTR + lb_n + i] = bh;
            BL[lb_kp * PSTR + lb_n + i] = packbf2(x - hx, y - hy);
        }
    };

    float cacc[4][4][4] = {};

    ldreg(0);
    stsm(0);
    __syncthreads();

    const int nT = K / 32;
    for (int t = 0; t < nT; t++) {
        const int buf = t & 1;
        if (t + 1 < nT) ldreg((t + 1) * 32);

        const uint32_t ah_sh = smem_sh + 4 * (buf * GBUF);
        const uint32_t al_sh = ah_sh + 4 * ABUF;
        const uint32_t* BPH = smx + buf * GBUF + 2 * ABUF;
        const uint32_t* BPL = BPH + PBUF;

        #pragma unroll
        for (int kk = 0; kk < 2; kk++) {
            const int kp = kk * 8 + a_kp_half;   // this lane's k-pair offset
            uint32_t aH[4][4], aL[4][4], bH[4][2], bL[4][2];
            #pragma unroll
            for (int mt = 0; mt < 4; mt++) {
                const int row = m_base + mt * 16 + a_row_in_tile;
                const uint32_t off = 4 * (row * ASTR + kp);
                LDSM_X4(aH[mt][0], aH[mt][1], aH[mt][2], aH[mt][3], ah_sh + off);
                LDSM_X4(aL[mt][0], aL[mt][1], aL[mt][2], aL[mt][3], al_sh + off);
            }
            const int base0 = (kk * 8 + cl4) * PSTR;
            const int base4 = (kk * 8 + cl4 + 4) * PSTR;
            #pragma unroll
            for (int nt = 0; nt < 4; nt++) {
                const int cc = n_base + nt * 8 + r;
                bH[nt][0] = BPH[base0 + cc];     bH[nt][1] = BPH[base4 + cc];
                bL[nt][0] = BPL[base0 + cc];     bL[nt][1] = BPL[base4 + cc];
            }
            #pragma unroll
            for (int mt = 0; mt < 4; mt++)
                #pragma unroll
                for (int nt = 0; nt < 4; nt++) {
                    MMA_BF16(cacc[mt][nt], aH[mt], bH[nt]);
                    MMA_BF16(cacc[mt][nt], aH[mt], bL[nt]);
                    MMA_BF16(cacc[mt][nt], aL[mt], bH[nt]);
                }
        }

        if (t + 1 < nT) {
            stsm(1 - buf);
            __syncthreads();
        }
    }

    // epilogue: c0/c1 at (row0, col,col+1); c2/c3 at (row0+8, ...)
    #pragma unroll
    for (int mt = 0; mt < 4; mt++) {
        #pragma unroll
        for (int nt = 0; nt < 4; nt++) {
            const int row0 = bm + m_base + mt * 16 + r;
            const int col  = bn + n_base + nt * 8 + 2 * cl4;
            float v0 = cacc[mt][nt][0], v1 = cacc[mt][nt][1];
            float v2 = cacc[mt][nt][2], v3 = cacc[mt][nt][3];
            if (bias) {
                const float bb0 = bias[col], bb1 = bias[col + 1];
                v0 += bb0; v1 += bb1; v2 += bb0; v3 += bb1;
            }
            float* p0 = &C[(size_t)row0 * N + col];
            float* p1 = &C[(size_t)(row0 + 8) * N + col];
            if (ACC) {
                float2 o0 = *(const float2*)p0;
                float2 o1 = *(const float2*)p1;
                v0 += o0.x; v1 += o0.y; v2 += o1.x; v3 += o1.y;
            }
            if (RELU) {
                v0 = fmaxf(v0, 0.f); v1 = fmaxf(v1, 0.f);
                v2 = fmaxf(v2, 0.f); v3 = fmaxf(v3, 0.f);
            }
            *(float2*)p0 = make_float2(v0, v1);
            *(float2*)p1 = make_float2(v2, v3);
        }
    }
}

// ============================================================================
// persistent TLSTM: all 256 steps in ONE kernel.
// Mainloop uses Blackwell packed fma.rn.f32x2 (FFMA2) + 16B loads:
// weights staged k-quad interleaved [k/4][lane][4]; h/c broadcast LDS.128.
// ============================================================================
__device__ __forceinline__ float sigmoidf_(float x) { return 1.f / (1.f + __expf(-x)); }

#define FMA_F32X2(d, a, b)                                                     \
    asm("fma.rn.f32x2 %0, %1, %2, %0;" : "+l"(d) : "l"(a), "l"(b))

__device__ __forceinline__ float f32x2_sum(unsigned long long v) {
    float2 f; memcpy(&f, &v, 8); return f.x + f.y;
}

__global__ __launch_bounds__(256, 1)
void tlstm_persistent(const float* __restrict__ u,    const float* __restrict__ ts,
                      const float* __restrict__ Wall, const float* __restrict__ bAll,
                      const float* __restrict__ Wd,   const float* __restrict__ bD,
                      float* h0b, float* c0b, float* h1b, float* c1b,
                      float* __restrict__ feat)
{
    extern __shared__ float sm[];
    float* ws  = sm;            // 32768 floats, [g][k/4][lane][4]
    float* wds = ws + 32768;    // 8192,  [k/4][lane][4]
    float* hs  = wds + 8192;    // 2048
    float* cs  = hs + 2048;     // 2048
    float* par = cs + 2048;     // 10240
    // total 55296 floats = 221184 bytes

    const int tid  = threadIdx.x;
    const int lane = tid & 31;
    const int wid  = tid >> 5;
    const int jt   = blockIdx.x & 7;
    const int rt   = blockIdx.x >> 3;
    const int j0   = jt * 32;
    const int r0   = rt * 8;
    const int j    = j0 + lane;
    const int brow = r0 + wid;

    // ---- stage weights once: k-quad interleaved for LDS.128 ----
    for (int idx = tid; idx < 4 * 256 * 32; idx += 256) {
        int g = idx >> 13;
        int k = (idx >> 5) & 255;
        int l = idx & 31;
        ws[g * 8192 + (k >> 2) * 128 + l * 4 + (k & 3)] = __ldg(&Wall[k * 1024 + g * 256 + j0 + l]);
    }
    for (int idx = tid; idx < 256 * 32; idx += 256) {
        int k = idx >> 5;
        int l = idx & 31;
        wds[(k >> 2) * 128 + l * 4 + (k & 3)] = __ldg(&Wd[k * 256 + j0 + l]);
    }
    const float b0 = bAll[j], b1 = bAll[j + 256], b2 = bAll[j + 512], b3 = bAll[j + 768];
    const float bd = bD[j];
    __syncthreads();

    for (int s = 0; s < S_SZ; s++) {
        const float* hprev = (s & 1) ? h1b : h0b;
        const float* cprev = (s & 1) ? c1b : c0b;
        float* hnew = (s & 1) ? h0b : h1b;
        float* cnew = (s & 1) ? c0b : c1b;

        // constant per-step operands BEFORE the spin: DRAM latency overlaps barrier
        const float tt = ts[brow * S_SZ + s];
        const float* um = u + ((size_t)brow * S_SZ + s) * 1024;
        const float u0 = um[j], u1 = um[j + 256], u2 = um[j + 512], u3 = um[j + 768];

        if (s > 0) {
            if (tid == 0) {
                while (atomicAdd(&g_gen2[rt], 0u) < (unsigned)s) __nanosleep(32);
            }
            __syncthreads();
        }

        if (s == 0) {
            for (int i = tid; i < 512; i += 256) {
                *(float4*)&hs[i * 4] = make_float4(0.f, 0.f, 0.f, 0.f);
                *(float4*)&cs[i * 4] = make_float4(0.f, 0.f, 0.f, 0.f);
            }
        } else {
            for (int i = tid; i < 512; i += 256) {
                int e = i * 4;
                int rr = e >> 8;
                int cc = e & 255;
                *(float4*)&hs[e] = __ldcg((const float4*)&hprev[(r0 + rr) * 256 + cc]);
                *(float4*)&cs[e] = __ldcg((const float4*)&cprev[(r0 + rr) * 256 + cc]);
            }
        }
        __syncthreads();

        // ---- split-K mainloop (FFMA2): warp `wid` covers k in [wid*32, +32) ----
        unsigned long long acc2[8][5];
        #pragma unroll
        for (int rr = 0; rr < 8; rr++)
            #pragma unroll
            for (int g = 0; g < 5; g++) acc2[rr][g] = 0ull;

        const int kb = wid * 32;
        #pragma unroll
        for (int k4 = 0; k4 < 8; k4++) {
            const int k  = kb + k4 * 4;
            const int wb = (k >> 2) * 128 + lane * 4;
            const ulonglong2 wdv = *(const ulonglong2*)&wds[wb];
            const ulonglong2 w0v = *(const ulonglong2*)&ws[wb];
            const ulonglong2 w1v = *(const ulonglong2*)&ws[8192  + wb];
            const ulonglong2 w2v = *(const ulonglong2*)&ws[16384 + wb];
            const ulonglong2 w3v = *(const ulonglong2*)&ws[24576 + wb];
            #pragma unroll
            for (int rr = 0; rr < 8; rr++) {
                const ulonglong2 h2 = *(const ulonglong2*)&hs[rr * 256 + k];
                const ulonglong2 c2 = *(const ulonglong2*)&cs[rr * 256 + k];
                FMA_F32X2(acc2[rr][0], h2.x, w0v.x);  FMA_F32X2(acc2[rr][0], h2.y, w0v.y);
                FMA_F32X2(acc2[rr][1], h2.x, w1v.x);  FMA_F32X2(acc2[rr][1], h2.y, w1v.y);
                FMA_F32X2(acc2[rr][2], h2.x, w2v.x);  FMA_F32X2(acc2[rr][2], h2.y, w2v.y);
                FMA_F32X2(acc2[rr][3], h2.x, w3v.x);  FMA_F32X2(acc2[rr][3], h2.y, w3v.y);
                FMA_F32X2(acc2[rr][4], c2.x, wdv.x);  FMA_F32X2(acc2[rr][4], c2.y, wdv.y);
            }
        }

        #pragma unroll
        for (int rr = 0; rr < 8; rr++)
            #pragma unroll
            for (int g = 0; g < 5; g++)
                par[((wid * 8 + rr) * 5 + g) * 32 + lane] = f32x2_sum(acc2[rr][g]);
        __syncthreads();

        // ---- reduce + gates: thread (wid=row, lane=col) owns one output ----
        float gv0 = 0.f, gv1 = 0.f, gv2 = 0.f, gv3 = 0.f, gv4 = 0.f;
        #pragma unroll
        for (int w = 0; w < 8; w++) {
            const int base = ((w * 8 + wid) * 5) * 32 + lane;
            gv0 += par[base];
            gv1 += par[base + 32];
            gv2 += par[base + 64];
            gv3 += par[base + 96];
            gv4 += par[base + 128];
        }

        const float cs1  = tanhf(gv4 + bd);
        const float cpv  = cs[wid * 256 + j];
        const float cadj = (cpv - cs1) + cs1 * tt;

        const float f  = sigmoidf_(gv0 + b0 + u0);
        const float ig = sigmoidf_(gv1 + b1 + u1);
        const float o  = sigmoidf_(gv2 + b2 + u2);
        const float ct = sigmoidf_(gv3 + b3 + u3);

        const float cn = f * cadj + ig * ct;
        const float hn = o * tanhf(cn);

        __stcg(&hnew[brow * 256 + j], hn);
        __stcg(&cnew[brow * 256 + j], cn);
        feat[((size_t)brow * S_SZ + s) * 256 + j] = hn;

        if (s < S_SZ - 1) {
            __threadfence();
            __syncthreads();
            if (tid == 0) {
                unsigned old = atomicAdd(&g_cnt2[rt], 1u);
                if (old == 7u) {
                    atomicExch(&g_cnt2[rt], 0u);
                    __threadfence();
                    atomicExch(&g_gen2[rt], (unsigned)(s + 1));
                }
            }
        }
    }
}

// ---------------- classifier ----------------
__global__ __launch_bounds__(256)
void cls_kernel(const float* __restrict__ feat, const float* __restrict__ w,
                const float* __restrict__ bb, float* __restrict__ out)
{
    const int warp = threadIdx.x >> 5;
    const int lane = threadIdx.x & 31;
    const int m = blockIdx.x * 8 + warp;
    const float* fr = feat + (size_t)m * 256;
    float s = 0.f;
    #pragma unroll
    for (int i = 0; i < 8; i++) s += fr[lane + 32 * i] * w[lane + 32 * i];
    #pragma unroll
    for (int off = 16; off; off >>= 1) s += __shfl_down_sync(0xffffffffu, s, off);
    if (lane == 0) out[m] = s + bb[0];
}

__global__ void init_kernel()
{
    int i = threadIdx.x;
    if (i < 16) { g_cnt2[i] = 0u; g_gen2[i] = 0u; }
}

// ---------------- launch ----------------
extern "C" void kernel_launch(void* const* d_in, const int* in_sizes, int n_in,
                              void* d_out, int out_size)
{
    const float* x      = (const float*)d_in[0];
    const float* stages = (const float*)d_in[1];
    const float* ts     = (const float*)d_in[2];
    const float* se_w1  = (const float*)d_in[3];
    const float* se_b1  = (const float*)d_in[4];
    const float* se_w2  = (const float*)d_in[5];
    const float* se_b2  = (const float*)d_in[6];
    const float* se_w3  = (const float*)d_in[7];
    const float* se_b3  = (const float*)d_in[8];
    const float* Wall   = (const float*)d_in[9];
    const float* bAll   = (const float*)d_in[10];
    const float* Uall   = (const float*)d_in[11];
    const float* bU     = (const float*)d_in[12];
    const float* Wd     = (const float*)d_in[13];
    const float* bD     = (const float*)d_in[14];
    const float* clsw   = (const float*)d_in[15];
    const float* clsb   = (const float*)d_in[16];

    float* out = (float*)d_out;

    float *st1, *st2, *st3, *u, *hb, *cb;
    cudaGetSymbolAddress((void**)&st1, g_st1);
    cudaGetSymbolAddress((void**)&st2, g_st2);
    cudaGetSymbolAddress((void**)&st3, g_st3);
    cudaGetSymbolAddress((void**)&u,   g_u);
    cudaGetSymbolAddress((void**)&hb,  g_h);
    cudaGetSymbolAddress((void**)&cb,  g_c);
    float* h0 = hb;  float* h1 = hb + B_SZ * HID;
    float* c0 = cb;  float* c1 = cb + B_SZ * HID;

    float* feat = (out_size >= MS + MS * HID) ? (out + MS) : st2;

    const int gemm_smem = 2 * GBUF * (int)sizeof(uint32_t);      // 75776 B
    cudaFuncSetAttribute(bf16_gemm<true,  false>,
                         cudaFuncAttributeMaxDynamicSharedMemorySize, gemm_smem);
    cudaFuncSetAttribute(bf16_gemm<false, false>,
                         cudaFuncAttributeMaxDynamicSharedMemorySize, gemm_smem);
    cudaFuncSetAttribute(bf16_gemm<false, true >,
                         cudaFuncAttributeMaxDynamicSharedMemorySize, gemm_smem);
    const int lstm_smem = 55296 * (int)sizeof(float);            // 221184 B
    cudaFuncSetAttribute(tlstm_persistent,
                         cudaFuncAttributeMaxDynamicSharedMemorySize, lstm_smem);

    init_kernel<<<1, 32>>>();

    // stage-embedding MLP (se1 fp32 due to K=67; se2/se3 on tensor cores)
    sgemm_kernel<true, false><<<dim3(2, MS / 128), 256>>>(stages, se_w1, se_b1, st1, MS, 256, 67);
    bf16_gemm<true, false><<<dim3(4, MS / 128), 256, gemm_smem>>>(st1, se_w2, se_b2, st2, MS, 512, 256);
    bf16_gemm<true, false><<<dim3(8, MS / 128), 256, gemm_smem>>>(st2, se_w3, se_b3, st3, MS, 1024, 512);

    // u = x @ U[0:1024] + bU ; u += st3 @ U[1024:2048]  (concat avoided)
    bf16_gemm<false, false><<<dim3(8, MS / 128), 256, gemm_smem>>>(x,   Uall,               bU,      u, MS, 1024, 1024);
    bf16_gemm<false, true ><<<dim3(8, MS / 128), 256, gemm_smem>>>(st3, Uall + 1024 * 1024, nullptr, u, MS, 1024, 1024);

    // all 256 TLSTM steps in one persistent kernel
    tlstm_persistent<<<NBLK, 256, lstm_smem>>>(u, ts, Wall, bAll, Wd, bD,
                                               h0, c0, h1, c1, feat);

    // classifier
    cls_kernel<<<MS / 8, 256>>>(feat, clsw, clsb, out);
}

// round 13
// speedup vs baseline: 1.4737x; 1.0035x over previous
#include <cuda_runtime.h>
#include <cuda_bf16.h>
#include <math.h>
#include <stdint.h>
#include <string.h>

#define B_SZ 128
#define S_SZ 256
#define HID  256
#define MS   (B_SZ * S_SZ)   // 32768 rows
#define NBLK 128             // persistent LSTM grid (<=148 SMs -> all resident)

// ---------------- scratch (device globals; no allocation allowed) ----------------
__device__ float g_st1[MS * 256];
__device__ float g_st2[MS * 512];
__device__ float g_st3[MS * 1024];
__device__ float g_u  [MS * 1024];
__device__ float g_h  [2 * B_SZ * HID];
__device__ float g_c  [2 * B_SZ * HID];
__device__ unsigned g_cnt2[16];
__device__ unsigned g_gen2[16];

// ============================================================================
// fp32 SGEMM (used only for se1, K=67): BM=128,BN=128,BK=8, double-buffered.
// ============================================================================
template<bool RELU, bool ACC>
__global__ __launch_bounds__(256, 2)
void sgemm_kernel(const float* __restrict__ A, const float* __restrict__ Bm,
                  const float* __restrict__ bias, float* __restrict__ C,
                  int M, int N, int K)
{
    __shared__ float As[2][8][128];
    __shared__ float Bs[2][8][128];

    const int tid = threadIdx.x;
    const int tx  = tid & 15;
    const int ty  = tid >> 4;
    const int bm  = blockIdx.y * 128;
    const int bn  = blockIdx.x * 128;

    float acc[8][8] = {};

    const int a_base = tid * 4;
    const int am = a_base >> 3;
    const int ak = a_base & 7;
    const int bk = tid >> 5;
    const int bn4 = (tid & 31) * 4;

    float ra[4];
    float4 rb;

    auto ldreg = [&](int k0) {
        #pragma unroll
        for (int i = 0; i < 4; i++) {
            int gk = k0 + ak + i;
            ra[i] = (gk < K) ? A[(size_t)(bm + am) * K + gk] : 0.f;
        }
        if (k0 + bk < K) rb = *(const float4*)&Bm[(size_t)(k0 + bk) * N + bn + bn4];
        else             rb = make_float4(0.f, 0.f, 0.f, 0.f);
    };
    auto stsm = [&](int buf) {
        #pragma unroll
        for (int i = 0; i < 4; i++) As[buf][ak + i][am] = ra[i];
        *(float4*)&Bs[buf][bk][bn4] = rb;
    };

    ldreg(0);
    stsm(0);
    __syncthreads();

    const int nT = (K + 7) / 8;
    for (int t = 0; t < nT; t++) {
        const int buf = t & 1;
        if (t + 1 < nT) ldreg((t + 1) * 8);

        #pragma unroll
        for (int kk = 0; kk < 8; kk++) {
            float4 a0 = *(const float4*)&As[buf][kk][ty * 8];
            float4 a1 = *(const float4*)&As[buf][kk][ty * 8 + 4];
            float4 b0 = *(const float4*)&Bs[buf][kk][tx * 8];
            float4 b1 = *(const float4*)&Bs[buf][kk][tx * 8 + 4];
            float av[8] = {a0.x, a0.y, a0.z, a0.w, a1.x, a1.y, a1.z, a1.w};
            float bv[8] = {b0.x, b0.y, b0.z, b0.w, b1.x, b1.y, b1.z, b1.w};
            #pragma unroll
            for (int i = 0; i < 8; i++)
                #pragma unroll
                for (int j = 0; j < 8; j++)
                    acc[i][j] += av[i] * bv[j];
        }

        if (t + 1 < nT) {
            stsm(1 - buf);
            __syncthreads();
        }
    }

    #pragma unroll
    for (int i = 0; i < 8; i++) {
        const size_t row = (size_t)(bm + ty * 8 + i);
        #pragma unroll
        for (int j = 0; j < 8; j += 4) {
            const int col = bn + tx * 8 + j;
            float4 v = make_float4(acc[i][j], acc[i][j + 1], acc[i][j + 2], acc[i][j + 3]);
            if (bias) {
                v.x += bias[col];     v.y += bias[col + 1];
                v.z += bias[col + 2]; v.w += bias[col + 3];
            }
            if (ACC) {
                float4 o = *(const float4*)&C[row * N + col];
                v.x += o.x; v.y += o.y; v.z += o.z; v.w += o.w;
            }
            if (RELU) {
                v.x = fmaxf(v.x, 0.f); v.y = fmaxf(v.y, 0.f);
                v.z = fmaxf(v.z, 0.f); v.w = fmaxf(v.w, 0.f);
            }
            *(float4*)&C[row * N + col] = v;
        }
    }
}

// ============================================================================
// split-bf16 tensor-core GEMM, ldmatrix A-fragments, 2 CTAs/SM.
// C = act(A[M,K] @ B[K,N] + bias (+C)); a = aH + aL; D += aH bH + aH bL + aL bH.
// BM=128, BN=128, BK=32. 8 warps (2x4), warp tile 64x32 via m16n8k16.
// A-fragments loaded per-mt (8 live regs) to fit the 128-reg / 2-CTA budget.
// ============================================================================
#define ASTR 20                       // A row stride in u32 (16 used + 4 pad)
#define ABUF 2560                     // 128 rows * ASTR
#define PSTR 136                      // B pair-row stride (u32)
#define PBUF 2176                     // 16 pair-rows * PSTR
#define GBUF 9472                     // ABUF*2 + PBUF*2 per stage
// stage layout: [AH(2560) | AL(2560) | BH(2176) | BL(2176)]

__device__ __forceinline__ uint32_t packbf2(float x, float y) {
    __nv_bfloat162 t = __floats2bfloat162_rn(x, y);   // x -> low 16, y -> high 16
    uint32_t r; memcpy(&r, &t, 4); return r;
}

#define MMA_BF16(cc, aa, bb)                                                   \
    asm volatile("mma.sync.aligned.m16n8k16.row.col.f32.bf16.bf16.f32 "        \
        "{%0,%1,%2,%3}, {%4,%5,%6,%7}, {%8,%9}, {%0,%1,%2,%3};"                \
        : "+f"((cc)[0]), "+f"((cc)[1]), "+f"((cc)[2]), "+f"((cc)[3])           \
        : "r"((aa)[0]), "r"((aa)[1]), "r"((aa)[2]), "r"((aa)[3]),              \
          "r"((bb)[0]), "r"((bb)[1]))

#define LDSM_X4(rr0, rr1, rr2, rr3, saddr)                                     \
    asm volatile("ldmatrix.sync.aligned.m8n8.x4.shared.b16 {%0,%1,%2,%3}, [%4];" \
        : "=r"(rr0), "=r"(rr1), "=r"(rr2), "=r"(rr3) : "r"(saddr))

template<bool RELU, bool ACC>
__global__ __launch_bounds__(256, 2)
void bf16_gemm(const float* __restrict__ A, const float* __restrict__ Bm,
               const float* __restrict__ bias, float* __restrict__ C,
               int M, int N, int K)
{
    extern __shared__ uint32_t smx[];
    const int tid  = threadIdx.x;
    const int lane = tid & 31;
    const int wid  = tid >> 5;
    const int wm   = wid >> 2;            // 0..1
    const int wn   = wid & 3;             // 0..3
    const int r    = lane >> 2;           // groupID 0..7
    const int cl4  = lane & 3;            // threadID_in_group 0..3
    const int bm   = blockIdx.y * 128;
    const int bn   = blockIdx.x * 128;
    const int m_base = wm * 64;
    const int n_base = wn * 32;

    const uint32_t smem_sh = (uint32_t)__cvta_generic_to_shared(smx);
    // ldmatrix lane addressing for A 16x16 tiles:
    // lanes 0-15 -> rows (lane&15), lanes 16-31 -> same rows, k-pair offset +4
    const int a_row_in_tile = lane & 15;
    const int a_kp_half     = (lane >> 4) * 4;

    // loader mapping: A: thread -> (row tid>>1, 16 consecutive k = 8 pairs)
    const int la_m   = tid >> 1;
    const int la_kp0 = (tid & 1) * 8;     // pair base 0 or 8
    // B: 16 pair-rows x 128 n; thread -> (pair tid>>4, 8 cols)
    const int lb_kp  = tid >> 4;          // 0..15
    const int lb_n   = (tid & 15) * 8;

    float4 ra[4];                         // A: 16 consecutive k floats
    float4 rb0[2], rb1[2];                // B: rows 2kp, 2kp+1, 8 cols each

    auto ldreg = [&](int k0) {
        const float* ap = A + (size_t)(bm + la_m) * K + k0 + la_kp0 * 2;
        #pragma unroll
        for (int i = 0; i < 4; i++) ra[i] = *(const float4*)(ap + 4 * i);
        const float* bp = Bm + (size_t)(k0 + 2 * lb_kp) * N + bn + lb_n;
        rb0[0] = *(const float4*)bp;       rb0[1] = *(const float4*)(bp + 4);
        rb1[0] = *(const float4*)(bp + N); rb1[1] = *(const float4*)(bp + N + 4);
    };
    auto stsm = [&](int buf) {
        uint32_t* AH = smx + buf * GBUF;
        uint32_t* AL = AH + ABUF;
        uint32_t* BH = smx + buf * GBUF + 2 * ABUF;
        uint32_t* BL = BH + PBUF;
        const float* av = (const float*)ra;
        uint32_t ph[8], pl[8];
        #pragma unroll
        for (int i = 0; i < 8; i++) {
            float x = av[2 * i], y = av[2 * i + 1];
            ph[i] = packbf2(x, y);
            float hx = __uint_as_float(ph[i] << 16);
            float hy = __uint_as_float(ph[i] & 0xffff0000u);
            pl[i] = packbf2(x - hx, y - hy);
        }
        const int abase = la_m * ASTR + la_kp0;
        *(uint4*)&AH[abase]     = make_uint4(ph[0], ph[1], ph[2], ph[3]);
        *(uint4*)&AH[abase + 4] = make_uint4(ph[4], ph[5], ph[6], ph[7]);
        *(uint4*)&AL[abase]     = make_uint4(pl[0], pl[1], pl[2], pl[3]);
        *(uint4*)&AL[abase + 4] = make_uint4(pl[4], pl[5], pl[6], pl[7]);
        const float* b0 = (const float*)rb0;
        const float* b1 = (const float*)rb1;
        #pragma unroll
        for (int i = 0; i < 8; i++) {
            float x = b0[i], y = b1[i];          // k even, k odd at col lb_n+i
            uint32_t bh = packbf2(x, y);
            float hx = __uint_as_float(bh << 16);
            float hy = __uint_as_float(bh & 0xffff0000u);
            BH[lb_kp * PSTR + lb_n + i] = bh;
            BL[lb_kp * PSTR + lb_n + i] = packbf2(x - hx, y - hy);
        }
    };

    float cacc[4][4][4] = {};

    ldreg(0);
    stsm(0);
    __syncthreads();

    const int nT = K / 32;
    for (int t = 0; t < nT; t++) {
        const int buf = t & 1;
        if (t + 1 < nT) ldreg((t + 1) * 32);

        const uint32_t ah_sh = smem_sh + 4 * (buf * GBUF);
        const uint32_t al_sh = ah_sh + 4 * ABUF;
        const uint32_t* BPH = smx + buf * GBUF + 2 * ABUF;
        const uint32_t* BPL = BPH + PBUF;

        #pragma unroll
        for (int kk = 0; kk < 2; kk++) {
            const int kp = kk * 8 + a_kp_half;   // this lane's k-pair offset
            const int base0 = (kk * 8 + cl4) * PSTR;
            const int base4 = (kk * 8 + cl4 + 4) * PSTR;
            uint32_t bH[4][2], bL[4][2];
            #pragma unroll
            for (int nt = 0; nt < 4; nt++) {
                const int cc = n_base + nt * 8 + r;
                bH[nt][0] = BPH[base0 + cc];     bH[nt][1] = BPH[base4 + cc];
                bL[nt][0] = BPL[base0 + cc];     bL[nt][1] = BPL[base4 + cc];
            }
            // A-fragments loaded per-mt: small live set -> 128-reg / 2-CTA fit
            #pragma unroll
            for (int mt = 0; mt < 4; mt++) {
                const int row = m_base + mt * 16 + a_row_in_tile;
                const uint32_t off = 4 * (row * ASTR + kp);
                uint32_t aH[4], aL[4];
                LDSM_X4(aH[0], aH[1], aH[2], aH[3], ah_sh + off);
                LDSM_X4(aL[0], aL[1], aL[2], aL[3], al_sh + off);
                #pragma unroll
                for (int nt = 0; nt < 4; nt++) {
                    MMA_BF16(cacc[mt][nt], aH, bH[nt]);
                    MMA_BF16(cacc[mt][nt], aH, bL[nt]);
                    MMA_BF16(cacc[mt][nt], aL, bH[nt]);
                }
            }
        }

        if (t + 1 < nT) {
            stsm(1 - buf);
            __syncthreads();
        }
    }

    // epilogue: c0/c1 at (row0, col,col+1); c2/c3 at (row0+8, ...)
    #pragma unroll
    for (int mt = 0; mt < 4; mt++) {
        #pragma unroll
        for (int nt = 0; nt < 4; nt++) {
            const int row0 = bm + m_base + mt * 16 + r;
            const int col  = bn + n_base + nt * 8 + 2 * cl4;
            float v0 = cacc[mt][nt][0], v1 = cacc[mt][nt][1];
            float v2 = cacc[mt][nt][2], v3 = cacc[mt][nt][3];
            if (bias) {
                const float bb0 = bias[col], bb1 = bias[col + 1];
                v0 += bb0; v1 += bb1; v2 += bb0; v3 += bb1;
            }
            float* p0 = &C[(size_t)row0 * N + col];
            float* p1 = &C[(size_t)(row0 + 8) * N + col];
            if (ACC) {
                float2 o0 = *(const float2*)p0;
                float2 o1 = *(const float2*)p1;
                v0 += o0.x; v1 += o0.y; v2 += o1.x; v3 += o1.y;
            }
            if (RELU) {
                v0 = fmaxf(v0, 0.f); v1 = fmaxf(v1, 0.f);
                v2 = fmaxf(v2, 0.f); v3 = fmaxf(v3, 0.f);
            }
            *(float2*)p0 = make_float2(v0, v1);
            *(float2*)p1 = make_float2(v2, v3);
        }
    }
}

// ============================================================================
// persistent TLSTM: all 256 steps in ONE kernel.
// Mainloop uses Blackwell packed fma.rn.f32x2 (FFMA2) + 16B loads:
// weights staged k-quad interleaved [k/4][lane][4]; h/c broadcast LDS.128.
// ============================================================================
__device__ __forceinline__ float sigmoidf_(float x) { return 1.f / (1.f + __expf(-x)); }

#define FMA_F32X2(d, a, b)                                                     \
    asm("fma.rn.f32x2 %0, %1, %2, %0;" : "+l"(d) : "l"(a), "l"(b))

__device__ __forceinline__ float f32x2_sum(unsigned long long v) {
    float2 f; memcpy(&f, &v, 8); return f.x + f.y;
}

__global__ __launch_bounds__(256, 1)
void tlstm_persistent(const float* __restrict__ u,    const float* __restrict__ ts,
                      const float* __restrict__ Wall, const float* __restrict__ bAll,
                      const float* __restrict__ Wd,   const float* __restrict__ bD,
                      float* h0b, float* c0b, float* h1b, float* c1b,
                      float* __restrict__ feat)
{
    extern __shared__ float sm[];
    float* ws  = sm;            // 32768 floats, [g][k/4][lane][4]
    float* wds = ws + 32768;    // 8192,  [k/4][lane][4]
    float* hs  = wds + 8192;    // 2048
    float* cs  = hs + 2048;     // 2048
    float* par = cs + 2048;     // 10240
    // total 55296 floats = 221184 bytes

    const int tid  = threadIdx.x;
    const int lane = tid & 31;
    const int wid  = tid >> 5;
    const int jt   = blockIdx.x & 7;
    const int rt   = blockIdx.x >> 3;
    const int j0   = jt * 32;
    const int r0   = rt * 8;
    const int j    = j0 + lane;
    const int brow = r0 + wid;

    // ---- stage weights once: k-quad interleaved for LDS.128 ----
    for (int idx = tid; idx < 4 * 256 * 32; idx += 256) {
        int g = idx >> 13;
        int k = (idx >> 5) & 255;
        int l = idx & 31;
        ws[g * 8192 + (k >> 2) * 128 + l * 4 + (k & 3)] = __ldg(&Wall[k * 1024 + g * 256 + j0 + l]);
    }
    for (int idx = tid; idx < 256 * 32; idx += 256) {
        int k = idx >> 5;
        int l = idx & 31;
        wds[(k >> 2) * 128 + l * 4 + (k & 3)] = __ldg(&Wd[k * 256 + j0 + l]);
    }
    const float b0 = bAll[j], b1 = bAll[j + 256], b2 = bAll[j + 512], b3 = bAll[j + 768];
    const float bd = bD[j];
    __syncthreads();

    for (int s = 0; s < S_SZ; s++) {
        const float* hprev = (s & 1) ? h1b : h0b;
        const float* cprev = (s & 1) ? c1b : c0b;
        float* hnew = (s & 1) ? h0b : h1b;
        float* cnew = (s & 1) ? c0b : c1b;

        // constant per-step operands BEFORE the spin: DRAM latency overlaps barrier
        const float tt = ts[brow * S_SZ + s];
        const float* um = u + ((size_t)brow * S_SZ + s) * 1024;
        const float u0 = um[j], u1 = um[j + 256], u2 = um[j + 512], u3 = um[j + 768];

        if (s > 0) {
            if (tid == 0) {
                while (atomicAdd(&g_gen2[rt], 0u) < (unsigned)s) __nanosleep(32);
            }
            __syncthreads();
        }

        if (s == 0) {
            for (int i = tid; i < 512; i += 256) {
                *(float4*)&hs[i * 4] = make_float4(0.f, 0.f, 0.f, 0.f);
                *(float4*)&cs[i * 4] = make_float4(0.f, 0.f, 0.f, 0.f);
            }
        } else {
            for (int i = tid; i < 512; i += 256) {
                int e = i * 4;
                int rr = e >> 8;
                int cc = e & 255;
                *(float4*)&hs[e] = __ldcg((const float4*)&hprev[(r0 + rr) * 256 + cc]);
                *(float4*)&cs[e] = __ldcg((const float4*)&cprev[(r0 + rr) * 256 + cc]);
            }
        }
        __syncthreads();

        // ---- split-K mainloop (FFMA2): warp `wid` covers k in [wid*32, +32) ----
        unsigned long long acc2[8][5];
        #pragma unroll
        for (int rr = 0; rr < 8; rr++)
            #pragma unroll
            for (int g = 0; g < 5; g++) acc2[rr][g] = 0ull;

        const int kb = wid * 32;
        #pragma unroll
        for (int k4 = 0; k4 < 8; k4++) {
            const int k  = kb + k4 * 4;
            const int wb = (k >> 2) * 128 + lane * 4;
            const ulonglong2 wdv = *(const ulonglong2*)&wds[wb];
            const ulonglong2 w0v = *(const ulonglong2*)&ws[wb];
            const ulonglong2 w1v = *(const ulonglong2*)&ws[8192  + wb];
            const ulonglong2 w2v = *(const ulonglong2*)&ws[16384 + wb];
            const ulonglong2 w3v = *(const ulonglong2*)&ws[24576 + wb];
            #pragma unroll
            for (int rr = 0; rr < 8; rr++) {
                const ulonglong2 h2 = *(const ulonglong2*)&hs[rr * 256 + k];
                const ulonglong2 c2 = *(const ulonglong2*)&cs[rr * 256 + k];
                FMA_F32X2(acc2[rr][0], h2.x, w0v.x);  FMA_F32X2(acc2[rr][0], h2.y, w0v.y);
                FMA_F32X2(acc2[rr][1], h2.x, w1v.x);  FMA_F32X2(acc2[rr][1], h2.y, w1v.y);
                FMA_F32X2(acc2[rr][2], h2.x, w2v.x);  FMA_F32X2(acc2[rr][2], h2.y, w2v.y);
                FMA_F32X2(acc2[rr][3], h2.x, w3v.x);  FMA_F32X2(acc2[rr][3], h2.y, w3v.y);
                FMA_F32X2(acc2[rr][4], c2.x, wdv.x);  FMA_F32X2(acc2[rr][4], c2.y, wdv.y);
            }
        }

        #pragma unroll
        for (int rr = 0; rr < 8; rr++)
            #pragma unroll
            for (int g = 0; g < 5; g++)
                par[((wid * 8 + rr) * 5 + g) * 32 + lane] = f32x2_sum(acc2[rr][g]);
        __syncthreads();

        // ---- reduce + gates: thread (wid=row, lane=col) owns one output ----
        float gv0 = 0.f, gv1 = 0.f, gv2 = 0.f, gv3 = 0.f, gv4 = 0.f;
        #pragma unroll
        for (int w = 0; w < 8; w++) {
            const int base = ((w * 8 + wid) * 5) * 32 + lane;
            gv0 += par[base];
            gv1 += par[base + 32];
            gv2 += par[base + 64];
            gv3 += par[base + 96];
            gv4 += par[base + 128];
        }

        const float cs1  = tanhf(gv4 + bd);
        const float cpv  = cs[wid * 256 + j];
        const float cadj = (cpv - cs1) + cs1 * tt;

        const float f  = sigmoidf_(gv0 + b0 + u0);
        const float ig = sigmoidf_(gv1 + b1 + u1);
        const float o  = sigmoidf_(gv2 + b2 + u2);
        const float ct = sigmoidf_(gv3 + b3 + u3);

        const float cn = f * cadj + ig * ct;
        const float hn = o * tanhf(cn);

        __stcg(&hnew[brow * 256 + j], hn);
        __stcg(&cnew[brow * 256 + j], cn);
        feat[((size_t)brow * S_SZ + s) * 256 + j] = hn;

        if (s < S_SZ - 1) {
            __threadfence();
            __syncthreads();
            if (tid == 0) {
                unsigned old = atomicAdd(&g_cnt2[rt], 1u);
                if (old == 7u) {
                    atomicExch(&g_cnt2[rt], 0u);
                    __threadfence();
                    atomicExch(&g_gen2[rt], (unsigned)(s + 1));
                }
            }
        }
    }
}

// ---------------- classifier ----------------
__global__ __launch_bounds__(256)
void cls_kernel(const float* __restrict__ feat, const float* __restrict__ w,
                const float* __restrict__ bb, float* __restrict__ out)
{
    const int warp = threadIdx.x >> 5;
    const int lane = threadIdx.x & 31;
    const int m = blockIdx.x * 8 + warp;
    const float* fr = feat + (size_t)m * 256;
    float s = 0.f;
    #pragma unroll
    for (int i = 0; i < 8; i++) s += fr[lane + 32 * i] * w[lane + 32 * i];
    #pragma unroll
    for (int off = 16; off; off >>= 1) s += __shfl_down_sync(0xffffffffu, s, off);
    if (lane == 0) out[m] = s + bb[0];
}

__global__ void init_kernel()
{
    int i = threadIdx.x;
    if (i < 16) { g_cnt2[i] = 0u; g_gen2[i] = 0u; }
}

// ---------------- launch ----------------
extern "C" void kernel_launch(void* const* d_in, const int* in_sizes, int n_in,
                              void* d_out, int out_size)
{
    const float* x      = (const float*)d_in[0];
    const float* stages = (const float*)d_in[1];
    const float* ts     = (const float*)d_in[2];
    const float* se_w1  = (const float*)d_in[3];
    const float* se_b1  = (const float*)d_in[4];
    const float* se_w2  = (const float*)d_in[5];
    const float* se_b2  = (const float*)d_in[6];
    const float* se_w3  = (const float*)d_in[7];
    const float* se_b3  = (const float*)d_in[8];
    const float* Wall   = (const float*)d_in[9];
    const float* bAll   = (const float*)d_in[10];
    const float* Uall   = (const float*)d_in[11];
    const float* bU     = (const float*)d_in[12];
    const float* Wd     = (const float*)d_in[13];
    const float* bD     = (const float*)d_in[14];
    const float* clsw   = (const float*)d_in[15];
    const float* clsb   = (const float*)d_in[16];

    float* out = (float*)d_out;

    float *st1, *st2, *st3, *u, *hb, *cb;
    cudaGetSymbolAddress((void**)&st1, g_st1);
    cudaGetSymbolAddress((void**)&st2, g_st2);
    cudaGetSymbolAddress((void**)&st3, g_st3);
    cudaGetSymbolAddress((void**)&u,   g_u);
    cudaGetSymbolAddress((void**)&hb,  g_h);
    cudaGetSymbolAddress((void**)&cb,  g_c);
    float* h0 = hb;  float* h1 = hb + B_SZ * HID;
    float* c0 = cb;  float* c1 = cb + B_SZ * HID;

    float* feat = (out_size >= MS + MS * HID) ? (out + MS) : st2;

    const int gemm_smem = 2 * GBUF * (int)sizeof(uint32_t);      // 75776 B
    cudaFuncSetAttribute(bf16_gemm<true,  false>,
                         cudaFuncAttributeMaxDynamicSharedMemorySize, gemm_smem);
    cudaFuncSetAttribute(bf16_gemm<false, false>,
                         cudaFuncAttributeMaxDynamicSharedMemorySize, gemm_smem);
    cudaFuncSetAttribute(bf16_gemm<false, true >,
                         cudaFuncAttributeMaxDynamicSharedMemorySize, gemm_smem);
    const int lstm_smem = 55296 * (int)sizeof(float);            // 221184 B
    cudaFuncSetAttribute(tlstm_persistent,
                         cudaFuncAttributeMaxDynamicSharedMemorySize, lstm_smem);

    init_kernel<<<1, 32>>>();

    // stage-embedding MLP (se1 fp32 due to K=67; se2/se3 on tensor cores)
    sgemm_kernel<true, false><<<dim3(2, MS / 128), 256>>>(stages, se_w1, se_b1, st1, MS, 256, 67);
    bf16_gemm<true, false><<<dim3(4, MS / 128), 256, gemm_smem>>>(st1, se_w2, se_b2, st2, MS, 512, 256);
    bf16_gemm<true, false><<<dim3(8, MS / 128), 256, gemm_smem>>>(st2, se_w3, se_b3, st3, MS, 1024, 512);

    // u = x @ U[0:1024] + bU ; u += st3 @ U[1024:2048]  (concat avoided)
    bf16_gemm<false, false><<<dim3(8, MS / 128), 256, gemm_smem>>>(x,   Uall,               bU,      u, MS, 1024, 1024);
    bf16_gemm<false, true ><<<dim3(8, MS / 128), 256, gemm_smem>>>(st3, Uall + 1024 * 1024, nullptr, u, MS, 1024, 1024);

    // all 256 TLSTM steps in one persistent kernel
    tlstm_persistent<<<NBLK, 256, lstm_smem>>>(u, ts, Wall, bAll, Wd, bD,
                                               h0, c0, h1, c1, feat);

    // classifier
    cls_kernel<<<MS / 8, 256>>>(feat, clsw, clsb, out);
}